// round 14
// baseline (speedup 1.0000x reference)
#include <cuda_runtime.h>
#include <cuda_bf16.h>
#include <math.h>
#include <stdint.h>

// Problem constants
#define NB 8
#define NT 2048
#define ND 1024
#define NH 64
#define SCALE 0.125f            // H^-0.5 = 1/8
#define NTILES (NT / 64)        // 32 q-tiles (64 rows)
#define KT128  (NT / 128)       // 16 k-tiles (128 cols) for colsum
#define QCHUNK 4                // q-chunks per k-tile (8 q-tiles each)

// Scratch (allocation-free: __device__ globals)
__device__ float g_v[NB * NT * NH];                    // V fp32 (from proj)
__device__ float g_part[QCHUNK * NB * NT];             // partial column sums
__device__ __nv_bfloat16 g_qh[NB * NT * NH];           // Q hi/lo bf16
__device__ __nv_bfloat16 g_ql[NB * NT * NH];
__device__ __nv_bfloat16 g_kh[NB * NT * NH];           // K hi/lo bf16
__device__ __nv_bfloat16 g_kl[NB * NT * NH];
__device__ __nv_bfloat16 g_v2h[NB * NT * NH];          // V' = V/colsum hi/lo
__device__ __nv_bfloat16 g_v2l[NB * NT * NH];
__device__ __nv_bfloat16 g_pTh[(size_t)NB * NT * NT];  // P^T hi: [b][k][q] 67MB
__device__ __nv_bfloat16 g_pTl[(size_t)NB * NT * NT];  // P^T lo
// W transposed + split: [hilo][mat][n=64][k=1024] bf16
__device__ __nv_bfloat16 g_wb[2 * 3 * 64 * 1024];

// ---------------------------------------------------------------------------
// Helpers: legacy tensor path (compute_103-legal): ldmatrix + mma.sync bf16,
// plus cp.async (Ampere+) for async gmem->smem pipelines.
// ---------------------------------------------------------------------------
__device__ __forceinline__ uint32_t smem_u32(const void* p) {
    uint32_t a;
    asm("{ .reg .u64 t; cvta.to.shared.u64 t, %1; cvt.u32.u64 %0, t; }"
        : "=r"(a) : "l"(p));
    return a;
}
#define LDSM_X4(r0, r1, r2, r3, a)                                              \
    asm volatile("ldmatrix.sync.aligned.m8n8.x4.shared.b16 {%0,%1,%2,%3}, [%4];" \
                 : "=r"(r0), "=r"(r1), "=r"(r2), "=r"(r3) : "r"(a))
#define LDSM_X2(r0, r1, a)                                                      \
    asm volatile("ldmatrix.sync.aligned.m8n8.x2.shared.b16 {%0,%1}, [%2];"      \
                 : "=r"(r0), "=r"(r1) : "r"(a))
#define LDSM_X4_T(r0, r1, r2, r3, a)                                            \
    asm volatile("ldmatrix.sync.aligned.m8n8.x4.trans.shared.b16 {%0,%1,%2,%3}, [%4];" \
                 : "=r"(r0), "=r"(r1), "=r"(r2), "=r"(r3) : "r"(a))
#define LDSM_X2_T(r0, r1, a)                                                    \
    asm volatile("ldmatrix.sync.aligned.m8n8.x2.trans.shared.b16 {%0,%1}, [%2];" \
                 : "=r"(r0), "=r"(r1) : "r"(a))
#define MMA_BF16(d, a, b)                                                       \
    asm volatile("mma.sync.aligned.m16n8k16.row.col.f32.bf16.bf16.f32 "         \
                 "{%0,%1,%2,%3}, {%4,%5,%6,%7}, {%8,%9}, {%0,%1,%2,%3};"        \
                 : "+f"((d)[0]), "+f"((d)[1]), "+f"((d)[2]), "+f"((d)[3])       \
                 : "r"((a)[0]), "r"((a)[1]), "r"((a)[2]), "r"((a)[3]),          \
                   "r"((b)[0]), "r"((b)[1]))

__device__ __forceinline__ void cp_async16(uint32_t smem, const void* g) {
    asm volatile("cp.async.cg.shared.global [%0], [%1], 16;"
                 :: "r"(smem), "l"(g) : "memory");
}
#define CP_COMMIT() asm volatile("cp.async.commit_group;" ::: "memory")
#define CP_WAIT(N)  asm volatile("cp.async.wait_group " #N ";" ::: "memory")

// Swizzles (16B units). 64B rows (proj) / 128B rows (colsum, out).
__device__ __forceinline__ uint32_t swzA(int r, int u) {
    return (uint32_t)(r * 64 + ((u ^ ((r >> 1) & 3)) << 4));
}
__device__ __forceinline__ uint32_t swz128(int r, int u) {
    return (uint32_t)(r * 128 + ((u ^ (r & 7)) << 4));
}
__device__ __forceinline__ void bf16split(float f, __nv_bfloat16& h, __nv_bfloat16& l) {
    h = __float2bfloat16_rn(f);
    l = __float2bfloat16_rn(f - __bfloat162float(h));
}

// ---------------------------------------------------------------------------
// Kernel 0: W -> transposed, bf16 hi/lo split, B layout [hilo][mat][n][k].
// ---------------------------------------------------------------------------
__global__ __launch_bounds__(256) void wconv_kernel(
    const float* __restrict__ Wq, const float* __restrict__ Wk,
    const float* __restrict__ Wv)
{
    __shared__ float tile[64 * 65];
    const int mat = blockIdx.x >> 4;
    const int k0  = (blockIdx.x & 15) * 64;
    const float* W = (mat == 0) ? Wq : (mat == 1) ? Wk : Wv;
    const int tid = threadIdx.x;

#pragma unroll
    for (int l = 0; l < 16; l++) {
        int idx = tid + l * 256;
        int k = idx >> 6, n = idx & 63;
        tile[k * 65 + n] = W[(k0 + k) * NH + n];
    }
    __syncthreads();
#pragma unroll
    for (int l = 0; l < 16; l++) {
        int idx = tid + l * 256;
        int n = idx >> 6, k = idx & 63;
        __nv_bfloat16 h, lo;
        bf16split(tile[k * 65 + n], h, lo);
        g_wb[((0 * 3 + mat) * 64 + n) * 1024 + k0 + k] = h;
        g_wb[((1 * 3 + mat) * 64 + n) * 1024 + k0 + k] = lo;
    }
}

// ---------------------------------------------------------------------------
// Kernel 1: projection GEMM via mma.sync bf16, split-fp32 (3 terms).
// Pipelined: A(x) register-prefetched one chunk ahead (cvt at STS time);
// B(W) double-buffered via cp.async, committed one chunk ahead.
// Dynamic smem 64KB: A hi 8K | A lo 8K | B stage0 24K | B stage1 24K.
// ---------------------------------------------------------------------------
#define PJ_ALO 8192
#define PJ_B(s) (16384 + (s) * 24576)
#define PJ_SMEM 65536

__global__ __launch_bounds__(256) void projmma_kernel(const float* __restrict__ x)
{
    extern __shared__ __align__(16) char sm[];
    const uint32_t sb = smem_u32(sm);

    const int tid  = threadIdx.x;
    const int wid  = tid >> 5;
    const int lane = tid & 31;
    const int row0 = blockIdx.x * 128;
    const int r0w  = (wid >> 1) * 32;
    const int c0w  = (wid & 1) * 96;

    float acc[2][12][4];
#pragma unroll
    for (int mi = 0; mi < 2; mi++)
#pragma unroll
        for (int ni = 0; ni < 12; ni++)
#pragma unroll
            for (int r = 0; r < 4; r++) acc[mi][ni][r] = 0.f;

    const int rA0 = r0w + (lane & 15);
    const int uHiA = lane >> 4;
    const int ldRow = (tid >> 3);             // A load: rows ldRow + 32*l
    const int ldKf  = (tid & 7) * 4;

    // B cp.async indexing (6 x 16B per thread per chunk)
    const char* bSrcBase[6];
    uint32_t bDstOff[6];
#pragma unroll
    for (int l = 0; l < 6; l++) {
        int idx = tid + l * 256;
        int rowhl = idx >> 2;
        int seg = idx & 3;
        int hilo = rowhl >= 192;
        int row = rowhl - hilo * 192;
        bSrcBase[l] = (const char*)g_wb + (size_t)rowhl * 2048 + seg * 16;
        bDstOff[l] = (uint32_t)(hilo * 12288) + swzA(row, seg);
    }

    // Prologue: A(0) into regs; B(0) -> stage 0
    float4 xv[4];
#pragma unroll
    for (int l = 0; l < 4; l++)
        xv[l] = *(const float4*)(x + (size_t)(row0 + ldRow + l * 32) * ND + 0 + ldKf);
#pragma unroll
    for (int l = 0; l < 6; l++)
        cp_async16(sb + PJ_B(0) + bDstOff[l], bSrcBase[l]);
    CP_COMMIT();

    for (int c = 0; c < 32; c++) {
        const int s = c & 1;
        __syncthreads();                     // MMA(c-1) done reading smA / B(s^1)
        // STS A(c) from prefetched regs, with bf16 hi/lo split
#pragma unroll
        for (int l = 0; l < 4; l++) {
            int row = ldRow + l * 32;
            __nv_bfloat162 h01, h23, l01, l23;
            bf16split(xv[l].x, h01.x, l01.x); bf16split(xv[l].y, h01.y, l01.y);
            bf16split(xv[l].z, h23.x, l23.x); bf16split(xv[l].w, h23.y, l23.y);
            uint32_t off = swzA(row, ldKf >> 3) + ((ldKf & 4) ? 8 : 0);
            uint2 hv = { *(uint32_t*)&h01, *(uint32_t*)&h23 };
            uint2 lv = { *(uint32_t*)&l01, *(uint32_t*)&l23 };
            *(uint2*)(sm + off) = hv;
            *(uint2*)(sm + PJ_ALO + off) = lv;
        }
        // Issue B(c+1) into the other stage (chunk stride = 32 bf16 = 64 bytes)
        if (c < 31) {
#pragma unroll
            for (int l = 0; l < 6; l++)
                cp_async16(sb + PJ_B(s ^ 1) + bDstOff[l],
                           bSrcBase[l] + (size_t)(c + 1) * 64);
            CP_COMMIT();
            CP_WAIT(1);                      // B(c) complete
        } else {
            CP_WAIT(0);
        }
        __syncthreads();                     // A STS + B(c) visible
        // Prefetch A(c+1) into regs (hidden under MMA)
        if (c < 31) {
#pragma unroll
            for (int l = 0; l < 4; l++)
                xv[l] = *(const float4*)(x + (size_t)(row0 + ldRow + l * 32) * ND
                                           + (c + 1) * 32 + ldKf);
        }

        const uint32_t bSt = sb + PJ_B(s);
#pragma unroll
        for (int st = 0; st < 2; st++) {
            uint32_t ah[2][4], al[2][4];
#pragma unroll
            for (int mi = 0; mi < 2; mi++) {
                int r = rA0 + mi * 16;
                uint32_t off = swzA(r, 2 * st + uHiA);
                LDSM_X4(ah[mi][0], ah[mi][1], ah[mi][2], ah[mi][3], sb + off);
                LDSM_X4(al[mi][0], al[mi][1], al[mi][2], al[mi][3], sb + PJ_ALO + off);
            }
#pragma unroll
            for (int ni = 0; ni < 12; ni++) {
                int rB = c0w + ni * 8 + (lane & 7);
                uint32_t off = swzA(rB, 2 * st + ((lane >> 3) & 1));
                uint32_t bh[2], bl[2];
                LDSM_X2(bh[0], bh[1], bSt + off);
                LDSM_X2(bl[0], bl[1], bSt + 12288 + off);
#pragma unroll
                for (int mi = 0; mi < 2; mi++) {
                    MMA_BF16(acc[mi][ni], ah[mi], bh);
                    MMA_BF16(acc[mi][ni], ah[mi], bl);
                    MMA_BF16(acc[mi][ni], al[mi], bh);
                }
            }
        }
    }

    // Epilogue: q,k -> bf16 hi/lo; v -> fp32
#pragma unroll
    for (int ni = 0; ni < 12; ni++) {
        int cg = c0w + ni * 8 + (lane & 3) * 2;
        int h = cg & 63;
#pragma unroll
        for (int mi = 0; mi < 2; mi++) {
            int r = row0 + r0w + mi * 16 + (lane >> 2);
            if (cg < 128) {
                __nv_bfloat16* dh = (cg < 64) ? g_qh : g_kh;
                __nv_bfloat16* dl = (cg < 64) ? g_ql : g_kl;
                __nv_bfloat162 h2, l2;
                bf16split(acc[mi][ni][0], h2.x, l2.x);
                bf16split(acc[mi][ni][1], h2.y, l2.y);
                *(__nv_bfloat162*)(dh + (size_t)r * NH + h) = h2;
                *(__nv_bfloat162*)(dl + (size_t)r * NH + h) = l2;
                bf16split(acc[mi][ni][2], h2.x, l2.x);
                bf16split(acc[mi][ni][3], h2.y, l2.y);
                *(__nv_bfloat162*)(dh + (size_t)(r + 8) * NH + h) = h2;
                *(__nv_bfloat162*)(dl + (size_t)(r + 8) * NH + h) = l2;
            } else {
                float2 v0 = {acc[mi][ni][0], acc[mi][ni][1]};
                float2 v1 = {acc[mi][ni][2], acc[mi][ni][3]};
                *(float2*)(g_v + (size_t)r * NH + h) = v0;
                *(float2*)(g_v + (size_t)(r + 8) * NH + h) = v1;
            }
        }
    }
}

// ---------------------------------------------------------------------------
// Kernel 2: colsum via HMMA, now with smem-staged coalesced P^T stores.
// Dynamic smem 80KB: KH 16K | KL 16K | QH 8K | QL 8K | stage-hi 16K | stage-lo 16K.
// Epilogue frags -> swizzled staging (conflict-free STS.32), then
// LDS.128 -> STG.128 full-line coalesced stores (8x fewer L1 wavefronts).
// ---------------------------------------------------------------------------
#define CS_KH 0
#define CS_KL 16384
#define CS_QH 32768
#define CS_QL 40960
#define CS_SH 49152
#define CS_SL 65536
#define CS_RED 49152            // overlays stage after final store
#define CS_SMEM 81920

__global__ __launch_bounds__(256) void colsum_kernel() {
    extern __shared__ __align__(16) char sm[];
    const uint32_t sb = smem_u32(sm);

    const int tid  = threadIdx.x;
    const int wid  = tid >> 5;
    const int lane = tid & 31;
    const int kt = blockIdx.x;
    const int c  = blockIdx.y;
    const int b  = blockIdx.z;
    const int k0 = kt * 128;
    const int wm = wid & 3;
    const int wn = wid >> 2;

    int qt_begin = 2 * kt; if (8 * c > qt_begin) qt_begin = 8 * c;
    const int qt_end = 8 * c + 8;

    if (qt_begin >= qt_end) {
        if (tid < 128) g_part[(c * NB + b) * NT + k0 + tid] = 0.f;
        return;
    }

#pragma unroll
    for (int l = 0; l < 8; l++) {
        int idx = tid + l * 256;
        int hilo = idx >> 10;
        int w = idx & 1023, r = w >> 3, u = w & 7;
        const __nv_bfloat16* src = (hilo ? g_kl : g_kh) + (size_t)(b * NT + k0 + r) * NH + u * 8;
        *(uint4*)(sm + (hilo ? CS_KL : CS_KH) + swz128(r, u)) = *(const uint4*)src;
    }

    float csum[4] = {0.f, 0.f, 0.f, 0.f};

    uint4 qreg[4];
    {
        const int q0 = qt_begin * 64;
#pragma unroll
        for (int l = 0; l < 4; l++) {
            int idx = tid + l * 256;
            int hilo = idx >> 9;
            int w = idx & 511, r = w >> 3, u = w & 7;
            const __nv_bfloat16* src = (hilo ? g_ql : g_qh) + (size_t)(b * NT + q0 + r) * NH + u * 8;
            qreg[l] = *(const uint4*)src;
        }
    }

    for (int qt = qt_begin; qt < qt_end; qt++) {
        const int q0 = qt * 64;
        __syncthreads();                     // prev STG done reading stage; Q reusable
#pragma unroll
        for (int l = 0; l < 4; l++) {
            int idx = tid + l * 256;
            int hilo = idx >> 9;
            int w = idx & 511, r = w >> 3, u = w & 7;
            *(uint4*)(sm + (hilo ? CS_QL : CS_QH) + swz128(r, u)) = qreg[l];
        }
        __syncthreads();
        if (qt + 1 < qt_end) {
            const int q1 = (qt + 1) * 64;
#pragma unroll
            for (int l = 0; l < 4; l++) {
                int idx = tid + l * 256;
                int hilo = idx >> 9;
                int w = idx & 511, r = w >> 3, u = w & 7;
                const __nv_bfloat16* src = (hilo ? g_ql : g_qh) + (size_t)(b * NT + q1 + r) * NH + u * 8;
                qreg[l] = *(const uint4*)src;
            }
        }

        float acc[2][4][4];
#pragma unroll
        for (int mi = 0; mi < 2; mi++)
#pragma unroll
            for (int ni = 0; ni < 4; ni++)
#pragma unroll
                for (int r = 0; r < 4; r++) acc[mi][ni][r] = 0.f;

#pragma unroll
        for (int s = 0; s < 4; s++) {
            uint32_t ah[2][4], al[2][4];
#pragma unroll
            for (int mi = 0; mi < 2; mi++) {
                int r = wm * 32 + mi * 16 + (lane & 15);
                int u = 2 * s + (lane >> 4);
                LDSM_X4(ah[mi][0], ah[mi][1], ah[mi][2], ah[mi][3], sb + CS_KH + swz128(r, u));
                LDSM_X4(al[mi][0], al[mi][1], al[mi][2], al[mi][3], sb + CS_KL + swz128(r, u));
            }
#pragma unroll
            for (int ni = 0; ni < 4; ni++) {
                int rB = wn * 32 + ni * 8 + (lane & 7);
                int u = 2 * s + ((lane >> 3) & 1);
                uint32_t bh[2], bl[2];
                LDSM_X2(bh[0], bh[1], sb + CS_QH + swz128(rB, u));
                LDSM_X2(bl[0], bl[1], sb + CS_QL + swz128(rB, u));
#pragma unroll
                for (int mi = 0; mi < 2; mi++) {
                    MMA_BF16(acc[mi][ni], ah[mi], bh);
                    MMA_BF16(acc[mi][ni], ah[mi], bl);
                    MMA_BF16(acc[mi][ni], al[mi], bh);
                }
            }
        }

        // Epilogue: mask + exp + csum; frags -> swizzled staging (hi & lo)
        const bool full = (q0 >= k0 + 128);
#pragma unroll
        for (int mi = 0; mi < 2; mi++) {
#pragma unroll
            for (int ni = 0; ni < 4; ni++) {
                int qg = q0 + wn * 32 + ni * 8 + 2 * (lane & 3);
#pragma unroll
                for (int half = 0; half < 2; half++) {
                    int kl = wm * 32 + mi * 16 + (lane >> 2) + 8 * half;
                    int kg = k0 + kl;
                    float d0 = acc[mi][ni][2 * half];
                    float d1 = acc[mi][ni][2 * half + 1];
                    float e0 = (full || qg >= kg) ? __expf(d0 * SCALE) : 0.f;
                    float e1 = (full || qg + 1 >= kg) ? __expf(d1 * SCALE) : 0.f;
                    csum[mi * 2 + half] += e0 + e1;
                    __nv_bfloat162 h2, l2;
                    bf16split(e0, h2.x, l2.x);
                    bf16split(e1, h2.y, l2.y);
                    uint32_t soff = swz128(kl, wn * 4 + ni) + 4 * (lane & 3);
                    *(uint32_t*)(sm + CS_SH + soff) = *(uint32_t*)&h2;
                    *(uint32_t*)(sm + CS_SL + soff) = *(uint32_t*)&l2;
                }
            }
        }
        __syncthreads();                     // staging complete

        // Coalesced store pass: LDS.128 -> STG.128 (full 128B lines)
#pragma unroll
        for (int l = 0; l < 4; l++) {
            int idx = tid + l * 256;         // 1024 x 16B per array
            int r = idx >> 3, u = idx & 7;
            uint4 vh = *(const uint4*)(sm + CS_SH + swz128(r, u));
            uint4 vl = *(const uint4*)(sm + CS_SL + swz128(r, u));
            size_t go = (size_t)(b * NT + k0 + r) * NT + q0 + u * 8;
            *(uint4*)(g_pTh + go) = vh;
            *(uint4*)(g_pTl + go) = vl;
        }
    }

    // Reduce csum: quad shfl, then cross-warp via smem (stage area reused)
#pragma unroll
    for (int i = 0; i < 4; i++) {
        csum[i] += __shfl_xor_sync(0xFFFFFFFF, csum[i], 1);
        csum[i] += __shfl_xor_sync(0xFFFFFFFF, csum[i], 2);
    }
    __syncthreads();                         // last STG pass done reading stage
    float* red = (float*)(sm + CS_RED);
    if ((lane & 3) == 0) {
#pragma unroll
        for (int mi = 0; mi < 2; mi++)
#pragma unroll
            for (int half = 0; half < 2; half++)
                red[wn * 128 + wm * 32 + mi * 16 + (lane >> 2) + 8 * half] = csum[mi * 2 + half];
    }
    __syncthreads();
    if (tid < 128)
        g_part[(c * NB + b) * NT + k0 + tid] = red[tid] + red[128 + tid];
}

// ---------------------------------------------------------------------------
// Kernel 3: v' = v * 1/colsum -> bf16 hi/lo
// ---------------------------------------------------------------------------
__global__ __launch_bounds__(256) void scalev_kernel() {
    int gid = blockIdx.x * 256 + threadIdx.x;
    int token = gid >> 4;
    int h0 = (gid & 15) * 4;
    int b = token >> 11, k = token & 2047;
    float s = g_part[(0 * NB + b) * NT + k] + g_part[(1 * NB + b) * NT + k]
            + g_part[(2 * NB + b) * NT + k] + g_part[(3 * NB + b) * NT + k];
    float rinv = 1.f / s;
    float4 v = *(const float4*)(g_v + (size_t)token * NH + h0);
    __nv_bfloat162 h01, h23, l01, l23;
    bf16split(v.x * rinv, h01.x, l01.x); bf16split(v.y * rinv, h01.y, l01.y);
    bf16split(v.z * rinv, h23.x, l23.x); bf16split(v.w * rinv, h23.y, l23.y);
    uint2 hv = { *(uint32_t*)&h01, *(uint32_t*)&h23 };
    uint2 lv = { *(uint32_t*)&l01, *(uint32_t*)&l23 };
    *(uint2*)(g_v2h + (size_t)token * NH + h0) = hv;
    *(uint2*)(g_v2l + (size_t)token * NH + h0) = lv;
}

// ---------------------------------------------------------------------------
// Kernel 4: out = P_causal @ V' via HMMA, 2-stage cp.async pipeline.
// Dynamic smem 64KB: stage s at s*32768: PH 8K | PL 8K | VH 8K | VL 8K.
// ---------------------------------------------------------------------------
#define OUT_SMEM 65536

__global__ __launch_bounds__(256, 2) void out_kernel(float* __restrict__ out) {
    extern __shared__ __align__(16) char sm[];
    const uint32_t sb = smem_u32(sm);

    const int tid  = threadIdx.x;
    const int wid  = tid >> 5;
    const int lane = tid & 31;
    const int qt = (NTILES - 1) - blockIdx.x;        // longest blocks first
    const int b  = blockIdx.y;
    const int q0 = qt * 64;
    const int wm = wid >> 1;
    const int wn = wid & 1;

    float acc[4][4];
#pragma unroll
    for (int ni = 0; ni < 4; ni++)
#pragma unroll
        for (int r = 0; r < 4; r++) acc[ni][r] = 0.f;

    // cp.async copy of one (P,V) tile pair into stage s
    auto issue_tile = [&](int kt, int s) {
        const int k0 = kt * 64;
#pragma unroll
        for (int l = 0; l < 8; l++) {
            int idx = tid + l * 256;
            int arr = idx >> 9;                      // 0:PH 1:PL 2:VH 3:VL
            int w = idx & 511, r = w >> 3, u = w & 7;
            const __nv_bfloat16* src;
            if (arr == 0)      src = g_pTh + (size_t)(b * NT + k0 + r) * NT + q0 + u * 8;
            else if (arr == 1) src = g_pTl + (size_t)(b * NT + k0 + r) * NT + q0 + u * 8;
            else if (arr == 2) src = g_v2h + (size_t)(b * NT + k0 + r) * NH + u * 8;
            else               src = g_v2l + (size_t)(b * NT + k0 + r) * NH + u * 8;
            cp_async16(sb + s * 32768 + arr * 8192 + swz128(r, u), src);
        }
        CP_COMMIT();
    };

    issue_tile(0, 0);

    for (int kt = 0; kt <= qt; kt++) {
        const int s = kt & 1;
        if (kt < qt) { issue_tile(kt + 1, s ^ 1); CP_WAIT(1); }
        else         { CP_WAIT(0); }
        __syncthreads();                 // stage s ready for all threads

        const uint32_t pHiB = sb + s * 32768;
        const uint32_t pLoB = pHiB + 8192;
        const uint32_t vHiB = pHiB + 16384;
        const uint32_t vLoB = pHiB + 24576;

#pragma unroll
        for (int st = 0; st < 4; st++) {
            int rA = st * 16 + (lane & 7) + 8 * (lane >> 4);
            int uA = wm * 2 + ((lane >> 3) & 1);
            uint32_t ah[4], al[4];
            LDSM_X4_T(ah[0], ah[1], ah[2], ah[3], pHiB + swz128(rA, uA));
            LDSM_X4_T(al[0], al[1], al[2], al[3], pLoB + swz128(rA, uA));
#pragma unroll
            for (int ni = 0; ni < 4; ni++) {
                int rB = st * 16 + (lane & 7) + 8 * ((lane >> 3) & 1);
                int uB = wn * 4 + ni;
                uint32_t bh[2], bl[2];
                LDSM_X2_T(bh[0], bh[1], vHiB + swz128(rB, uB));
                LDSM_X2_T(bl[0], bl[1], vLoB + swz128(rB, uB));
                MMA_BF16(acc[ni], ah, bh);
                MMA_BF16(acc[ni], ah, bl);
                MMA_BF16(acc[ni], al, bh);
            }
        }
        __syncthreads();                 // done reading stage s before reuse
    }

    // Epilogue: D frags -> out fp32
#pragma unroll
    for (int ni = 0; ni < 4; ni++) {
        int h = wn * 32 + ni * 8 + 2 * (lane & 3);
        int q = q0 + wm * 16 + (lane >> 2);
        float2 v0 = {acc[ni][0], acc[ni][1]};
        float2 v1 = {acc[ni][2], acc[ni][3]};
        *(float2*)(out + (size_t)(b * NT + q) * NH + h) = v0;
        *(float2*)(out + (size_t)(b * NT + q + 8) * NH + h) = v1;
    }
}

// ---------------------------------------------------------------------------
// Launch (graph-capturable, allocation-free, atomic-free -> deterministic).
// Input order per metadata: x, Wk, Wq, Wv.
// ---------------------------------------------------------------------------
extern "C" void kernel_launch(void* const* d_in, const int* in_sizes, int n_in,
                              void* d_out, int out_size) {
    const float* x  = (const float*)d_in[0];
    const float* Wk = (const float*)d_in[1];
    const float* Wq = (const float*)d_in[2];
    const float* Wv = (const float*)d_in[3];
    float* out = (float*)d_out;

    cudaFuncSetAttribute(projmma_kernel,
                         cudaFuncAttributeMaxDynamicSharedMemorySize, PJ_SMEM);
    cudaFuncSetAttribute(colsum_kernel,
                         cudaFuncAttributeMaxDynamicSharedMemorySize, CS_SMEM);
    cudaFuncSetAttribute(out_kernel,
                         cudaFuncAttributeMaxDynamicSharedMemorySize, OUT_SMEM);

    wconv_kernel<<<48, 256>>>(Wq, Wk, Wv);
    projmma_kernel<<<(NB * NT) / 128, 256, PJ_SMEM>>>(x);
    colsum_kernel<<<dim3(KT128, QCHUNK, NB), 256, CS_SMEM>>>();
    scalev_kernel<<<(NB * NT * NH / 4) / 256, 256>>>();
    out_kernel<<<dim3(NTILES, NB), 256, OUT_SMEM>>>(out);
}

// round 15
// speedup vs baseline: 1.4051x; 1.4051x over previous
#include <cuda_runtime.h>
#include <cuda_bf16.h>
#include <math.h>
#include <stdint.h>

// Problem constants
#define NB 8
#define NT 2048
#define ND 1024
#define NH 64
#define SCALE 0.125f            // H^-0.5 = 1/8
#define NTILES (NT / 64)        // 32 q-tiles (64 rows)
#define KT128  (NT / 128)       // 16 k-tiles (128 cols) for colsum
#define QCHUNK 4                // q-chunks per k-tile (8 q-tiles each)

// Scratch (allocation-free: __device__ globals)
__device__ float g_part[QCHUNK * NB * NT];             // partial column sums
__device__ float g_rinv[NB * NT];                      // 1 / colsum
__device__ __nv_bfloat16 g_qh[NB * NT * NH];           // Q hi/lo bf16
__device__ __nv_bfloat16 g_ql[NB * NT * NH];
__device__ __nv_bfloat16 g_kh[NB * NT * NH];           // K hi/lo bf16
__device__ __nv_bfloat16 g_kl[NB * NT * NH];
__device__ __nv_bfloat16 g_vh[NB * NT * NH];           // V hi/lo bf16
__device__ __nv_bfloat16 g_vl[NB * NT * NH];
// W transposed + split: [hilo][mat][n=64][k=1024] bf16
__device__ __nv_bfloat16 g_wb[2 * 3 * 64 * 1024];

// ---------------------------------------------------------------------------
// Helpers: legacy tensor path (compute_103-legal): ldmatrix + mma.sync bf16,
// plus cp.async (Ampere+) for async gmem->smem pipelines.
// ---------------------------------------------------------------------------
__device__ __forceinline__ uint32_t smem_u32(const void* p) {
    uint32_t a;
    asm("{ .reg .u64 t; cvta.to.shared.u64 t, %1; cvt.u32.u64 %0, t; }"
        : "=r"(a) : "l"(p));
    return a;
}
#define LDSM_X4(r0, r1, r2, r3, a)                                              \
    asm volatile("ldmatrix.sync.aligned.m8n8.x4.shared.b16 {%0,%1,%2,%3}, [%4];" \
                 : "=r"(r0), "=r"(r1), "=r"(r2), "=r"(r3) : "r"(a))
#define LDSM_X2(r0, r1, a)                                                      \
    asm volatile("ldmatrix.sync.aligned.m8n8.x2.shared.b16 {%0,%1}, [%2];"      \
                 : "=r"(r0), "=r"(r1) : "r"(a))
#define LDSM_X2_T(r0, r1, a)                                                    \
    asm volatile("ldmatrix.sync.aligned.m8n8.x2.trans.shared.b16 {%0,%1}, [%2];" \
                 : "=r"(r0), "=r"(r1) : "r"(a))
#define MMA_BF16(d, a, b)                                                       \
    asm volatile("mma.sync.aligned.m16n8k16.row.col.f32.bf16.bf16.f32 "         \
                 "{%0,%1,%2,%3}, {%4,%5,%6,%7}, {%8,%9}, {%0,%1,%2,%3};"        \
                 : "+f"((d)[0]), "+f"((d)[1]), "+f"((d)[2]), "+f"((d)[3])       \
                 : "r"((a)[0]), "r"((a)[1]), "r"((a)[2]), "r"((a)[3]),          \
                   "r"((b)[0]), "r"((b)[1]))

__device__ __forceinline__ void cp_async16(uint32_t smem, const void* g) {
    asm volatile("cp.async.cg.shared.global [%0], [%1], 16;"
                 :: "r"(smem), "l"(g) : "memory");
}
#define CP_COMMIT() asm volatile("cp.async.commit_group;" ::: "memory")
#define CP_WAIT(N)  asm volatile("cp.async.wait_group " #N ";" ::: "memory")

// Swizzles (16B units). 64B rows (proj) / 128B rows (colsum, out).
__device__ __forceinline__ uint32_t swzA(int r, int u) {
    return (uint32_t)(r * 64 + ((u ^ ((r >> 1) & 3)) << 4));
}
__device__ __forceinline__ uint32_t swz128(int r, int u) {
    return (uint32_t)(r * 128 + ((u ^ (r & 7)) << 4));
}
__device__ __forceinline__ void bf16split(float f, __nv_bfloat16& h, __nv_bfloat16& l) {
    h = __float2bfloat16_rn(f);
    l = __float2bfloat16_rn(f - __bfloat162float(h));
}
__device__ __forceinline__ uint32_t packbf(__nv_bfloat16 a, __nv_bfloat16 b) {
    __nv_bfloat162 t; t.x = a; t.y = b;
    return *(uint32_t*)&t;
}

// ---------------------------------------------------------------------------
// Kernel 0: W -> transposed, bf16 hi/lo split, B layout [hilo][mat][n][k].
// ---------------------------------------------------------------------------
__global__ __launch_bounds__(256) void wconv_kernel(
    const float* __restrict__ Wq, const float* __restrict__ Wk,
    const float* __restrict__ Wv)
{
    __shared__ float tile[64 * 65];
    const int mat = blockIdx.x >> 4;
    const int k0  = (blockIdx.x & 15) * 64;
    const float* W = (mat == 0) ? Wq : (mat == 1) ? Wk : Wv;
    const int tid = threadIdx.x;

#pragma unroll
    for (int l = 0; l < 16; l++) {
        int idx = tid + l * 256;
        int k = idx >> 6, n = idx & 63;
        tile[k * 65 + n] = W[(k0 + k) * NH + n];
    }
    __syncthreads();
#pragma unroll
    for (int l = 0; l < 16; l++) {
        int idx = tid + l * 256;
        int n = idx >> 6, k = idx & 63;
        __nv_bfloat16 h, lo;
        bf16split(tile[k * 65 + n], h, lo);
        g_wb[((0 * 3 + mat) * 64 + n) * 1024 + k0 + k] = h;
        g_wb[((1 * 3 + mat) * 64 + n) * 1024 + k0 + k] = lo;
    }
}

// ---------------------------------------------------------------------------
// Kernel 1: projection GEMM via mma.sync bf16, split-fp32 (3 terms).
// Pipelined (cp.async B, reg-prefetch A). q,k,v all emitted as bf16 hi/lo.
// ---------------------------------------------------------------------------
#define PJ_ALO 8192
#define PJ_B(s) (16384 + (s) * 24576)
#define PJ_SMEM 65536

__global__ __launch_bounds__(256) void projmma_kernel(const float* __restrict__ x)
{
    extern __shared__ __align__(16) char sm[];
    const uint32_t sb = smem_u32(sm);

    const int tid  = threadIdx.x;
    const int wid  = tid >> 5;
    const int lane = tid & 31;
    const int row0 = blockIdx.x * 128;
    const int r0w  = (wid >> 1) * 32;
    const int c0w  = (wid & 1) * 96;

    float acc[2][12][4];
#pragma unroll
    for (int mi = 0; mi < 2; mi++)
#pragma unroll
        for (int ni = 0; ni < 12; ni++)
#pragma unroll
            for (int r = 0; r < 4; r++) acc[mi][ni][r] = 0.f;

    const int rA0 = r0w + (lane & 15);
    const int uHiA = lane >> 4;
    const int ldRow = (tid >> 3);
    const int ldKf  = (tid & 7) * 4;

    const char* bSrcBase[6];
    uint32_t bDstOff[6];
#pragma unroll
    for (int l = 0; l < 6; l++) {
        int idx = tid + l * 256;
        int rowhl = idx >> 2;
        int seg = idx & 3;
        int hilo = rowhl >= 192;
        int row = rowhl - hilo * 192;
        bSrcBase[l] = (const char*)g_wb + (size_t)rowhl * 2048 + seg * 16;
        bDstOff[l] = (uint32_t)(hilo * 12288) + swzA(row, seg);
    }

    float4 xv[4];
#pragma unroll
    for (int l = 0; l < 4; l++)
        xv[l] = *(const float4*)(x + (size_t)(row0 + ldRow + l * 32) * ND + 0 + ldKf);
#pragma unroll
    for (int l = 0; l < 6; l++)
        cp_async16(sb + PJ_B(0) + bDstOff[l], bSrcBase[l]);
    CP_COMMIT();

    for (int c = 0; c < 32; c++) {
        const int s = c & 1;
        __syncthreads();
#pragma unroll
        for (int l = 0; l < 4; l++) {
            int row = ldRow + l * 32;
            __nv_bfloat162 h01, h23, l01, l23;
            bf16split(xv[l].x, h01.x, l01.x); bf16split(xv[l].y, h01.y, l01.y);
            bf16split(xv[l].z, h23.x, l23.x); bf16split(xv[l].w, h23.y, l23.y);
            uint32_t off = swzA(row, ldKf >> 3) + ((ldKf & 4) ? 8 : 0);
            uint2 hv = { *(uint32_t*)&h01, *(uint32_t*)&h23 };
            uint2 lv = { *(uint32_t*)&l01, *(uint32_t*)&l23 };
            *(uint2*)(sm + off) = hv;
            *(uint2*)(sm + PJ_ALO + off) = lv;
        }
        if (c < 31) {
#pragma unroll
            for (int l = 0; l < 6; l++)
                cp_async16(sb + PJ_B(s ^ 1) + bDstOff[l],
                           bSrcBase[l] + (size_t)(c + 1) * 64);
            CP_COMMIT();
            CP_WAIT(1);
        } else {
            CP_WAIT(0);
        }
        __syncthreads();
        if (c < 31) {
#pragma unroll
            for (int l = 0; l < 4; l++)
                xv[l] = *(const float4*)(x + (size_t)(row0 + ldRow + l * 32) * ND
                                           + (c + 1) * 32 + ldKf);
        }

        const uint32_t bSt = sb + PJ_B(s);
#pragma unroll
        for (int st = 0; st < 2; st++) {
            uint32_t ah[2][4], al[2][4];
#pragma unroll
            for (int mi = 0; mi < 2; mi++) {
                int r = rA0 + mi * 16;
                uint32_t off = swzA(r, 2 * st + uHiA);
                LDSM_X4(ah[mi][0], ah[mi][1], ah[mi][2], ah[mi][3], sb + off);
                LDSM_X4(al[mi][0], al[mi][1], al[mi][2], al[mi][3], sb + PJ_ALO + off);
            }
#pragma unroll
            for (int ni = 0; ni < 12; ni++) {
                int rB = c0w + ni * 8 + (lane & 7);
                uint32_t off = swzA(rB, 2 * st + ((lane >> 3) & 1));
                uint32_t bh[2], bl[2];
                LDSM_X2(bh[0], bh[1], bSt + off);
                LDSM_X2(bl[0], bl[1], bSt + 12288 + off);
#pragma unroll
                for (int mi = 0; mi < 2; mi++) {
                    MMA_BF16(acc[mi][ni], ah[mi], bh);
                    MMA_BF16(acc[mi][ni], ah[mi], bl);
                    MMA_BF16(acc[mi][ni], al[mi], bh);
                }
            }
        }
    }

    // Epilogue: q,k,v all -> bf16 hi/lo
#pragma unroll
    for (int ni = 0; ni < 12; ni++) {
        int cg = c0w + ni * 8 + (lane & 3) * 2;
        int h = cg & 63;
        __nv_bfloat16* dh = (cg < 64) ? g_qh : (cg < 128) ? g_kh : g_vh;
        __nv_bfloat16* dl = (cg < 64) ? g_ql : (cg < 128) ? g_kl : g_vl;
#pragma unroll
        for (int mi = 0; mi < 2; mi++) {
            int r = row0 + r0w + mi * 16 + (lane >> 2);
            __nv_bfloat162 h2, l2;
            bf16split(acc[mi][ni][0], h2.x, l2.x);
            bf16split(acc[mi][ni][1], h2.y, l2.y);
            *(__nv_bfloat162*)(dh + (size_t)r * NH + h) = h2;
            *(__nv_bfloat162*)(dl + (size_t)r * NH + h) = l2;
            bf16split(acc[mi][ni][2], h2.x, l2.x);
            bf16split(acc[mi][ni][3], h2.y, l2.y);
            *(__nv_bfloat162*)(dh + (size_t)(r + 8) * NH + h) = h2;
            *(__nv_bfloat162*)(dl + (size_t)(r + 8) * NH + h) = l2;
        }
    }
}

// ---------------------------------------------------------------------------
// Kernel 2: colsum via HMMA (R13 kernel with the P^T stores deleted —
// epilogue is mask/exp/csum only).
// ---------------------------------------------------------------------------
#define CS_KH 0
#define CS_KL 16384
#define CS_QH 32768
#define CS_QL 40960
#define CS_RED 32768

__global__ __launch_bounds__(256) void colsum_kernel() {
    __shared__ __align__(16) char sm[49152];
    const uint32_t sb = smem_u32(sm);

    const int tid  = threadIdx.x;
    const int wid  = tid >> 5;
    const int lane = tid & 31;
    const int kt = blockIdx.x;
    const int c  = blockIdx.y;
    const int b  = blockIdx.z;
    const int k0 = kt * 128;
    const int wm = wid & 3;
    const int wn = wid >> 2;

    int qt_begin = 2 * kt; if (8 * c > qt_begin) qt_begin = 8 * c;
    const int qt_end = 8 * c + 8;

    if (qt_begin >= qt_end) {
        if (tid < 128) g_part[(c * NB + b) * NT + k0 + tid] = 0.f;
        return;
    }

#pragma unroll
    for (int l = 0; l < 8; l++) {
        int idx = tid + l * 256;
        int hilo = idx >> 10;
        int w = idx & 1023, r = w >> 3, u = w & 7;
        const __nv_bfloat16* src = (hilo ? g_kl : g_kh) + (size_t)(b * NT + k0 + r) * NH + u * 8;
        *(uint4*)(sm + (hilo ? CS_KL : CS_KH) + swz128(r, u)) = *(const uint4*)src;
    }

    float csum[4] = {0.f, 0.f, 0.f, 0.f};

    uint4 qreg[4];
    {
        const int q0 = qt_begin * 64;
#pragma unroll
        for (int l = 0; l < 4; l++) {
            int idx = tid + l * 256;
            int hilo = idx >> 9;
            int w = idx & 511, r = w >> 3, u = w & 7;
            const __nv_bfloat16* src = (hilo ? g_ql : g_qh) + (size_t)(b * NT + q0 + r) * NH + u * 8;
            qreg[l] = *(const uint4*)src;
        }
    }

    for (int qt = qt_begin; qt < qt_end; qt++) {
        const int q0 = qt * 64;
        __syncthreads();
#pragma unroll
        for (int l = 0; l < 4; l++) {
            int idx = tid + l * 256;
            int hilo = idx >> 9;
            int w = idx & 511, r = w >> 3, u = w & 7;
            *(uint4*)(sm + (hilo ? CS_QL : CS_QH) + swz128(r, u)) = qreg[l];
        }
        __syncthreads();
        if (qt + 1 < qt_end) {
            const int q1 = (qt + 1) * 64;
#pragma unroll
            for (int l = 0; l < 4; l++) {
                int idx = tid + l * 256;
                int hilo = idx >> 9;
                int w = idx & 511, r = w >> 3, u = w & 7;
                const __nv_bfloat16* src = (hilo ? g_ql : g_qh) + (size_t)(b * NT + q1 + r) * NH + u * 8;
                qreg[l] = *(const uint4*)src;
            }
        }

        float acc[2][4][4];
#pragma unroll
        for (int mi = 0; mi < 2; mi++)
#pragma unroll
            for (int ni = 0; ni < 4; ni++)
#pragma unroll
                for (int r = 0; r < 4; r++) acc[mi][ni][r] = 0.f;

#pragma unroll
        for (int s = 0; s < 4; s++) {
            uint32_t ah[2][4], al[2][4];
#pragma unroll
            for (int mi = 0; mi < 2; mi++) {
                int r = wm * 32 + mi * 16 + (lane & 15);
                int u = 2 * s + (lane >> 4);
                LDSM_X4(ah[mi][0], ah[mi][1], ah[mi][2], ah[mi][3], sb + CS_KH + swz128(r, u));
                LDSM_X4(al[mi][0], al[mi][1], al[mi][2], al[mi][3], sb + CS_KL + swz128(r, u));
            }
#pragma unroll
            for (int ni = 0; ni < 4; ni++) {
                int rB = wn * 32 + ni * 8 + (lane & 7);
                int u = 2 * s + ((lane >> 3) & 1);
                uint32_t bh[2], bl[2];
                LDSM_X2(bh[0], bh[1], sb + CS_QH + swz128(rB, u));
                LDSM_X2(bl[0], bl[1], sb + CS_QL + swz128(rB, u));
#pragma unroll
                for (int mi = 0; mi < 2; mi++) {
                    MMA_BF16(acc[mi][ni], ah[mi], bh);
                    MMA_BF16(acc[mi][ni], ah[mi], bl);
                    MMA_BF16(acc[mi][ni], al[mi], bh);
                }
            }
        }

        const bool full = (q0 >= k0 + 128);
#pragma unroll
        for (int mi = 0; mi < 2; mi++) {
#pragma unroll
            for (int ni = 0; ni < 4; ni++) {
                int qg = q0 + wn * 32 + ni * 8 + 2 * (lane & 3);
#pragma unroll
                for (int half = 0; half < 2; half++) {
                    int kg = k0 + wm * 32 + mi * 16 + (lane >> 2) + 8 * half;
                    float d0 = acc[mi][ni][2 * half];
                    float d1 = acc[mi][ni][2 * half + 1];
                    float e0 = (full || qg >= kg) ? __expf(d0 * SCALE) : 0.f;
                    float e1 = (full || qg + 1 >= kg) ? __expf(d1 * SCALE) : 0.f;
                    csum[mi * 2 + half] += e0 + e1;
                }
            }
        }
    }

#pragma unroll
    for (int i = 0; i < 4; i++) {
        csum[i] += __shfl_xor_sync(0xFFFFFFFF, csum[i], 1);
        csum[i] += __shfl_xor_sync(0xFFFFFFFF, csum[i], 2);
    }
    __syncthreads();
    float* red = (float*)(sm + CS_RED);
    if ((lane & 3) == 0) {
#pragma unroll
        for (int mi = 0; mi < 2; mi++)
#pragma unroll
            for (int half = 0; half < 2; half++)
                red[wn * 128 + wm * 32 + mi * 16 + (lane >> 2) + 8 * half] = csum[mi * 2 + half];
    }
    __syncthreads();
    if (tid < 128)
        g_part[(c * NB + b) * NT + k0 + tid] = red[tid] + red[128 + tid];
}

// ---------------------------------------------------------------------------
// Kernel 3: rinv[b][k] = 1 / sum of partial column sums
// ---------------------------------------------------------------------------
__global__ __launch_bounds__(256) void rinv_kernel() {
    int gid = blockIdx.x * 256 + threadIdx.x;        // NB*NT = 16384
    int b = gid >> 11, k = gid & 2047;
    float s = g_part[(0 * NB + b) * NT + k] + g_part[(1 * NB + b) * NT + k]
            + g_part[(2 * NB + b) * NT + k] + g_part[(3 * NB + b) * NT + k];
    g_rinv[gid] = 1.f / s;
}

// ---------------------------------------------------------------------------
// Kernel 4: out = softmax-weights @ V, fully fused: recompute S via HMMA,
// exp*rinv+mask in registers (D-frag == A-frag layout trick), P@V via HMMA.
// 512 threads: warps = 4 q-groups (16q) x 4 k-quarters (16k). cp.async
// double-buffered K/V stages; end: 3-buffer smem reduction over k-quarters.
// smem 80KB: QH 8K | QL 8K | stage{0,1}: KH 8K KL 8K VH 8K VL 8K.
// ---------------------------------------------------------------------------
#define OQH 0
#define OQL 8192
#define OSTG(s) (16384 + (s) * 32768)
#define ORED OSTG(0)             // reduction reuses dead stage area (52KB<=64KB)
#define OUT_SMEM 81920

__global__ __launch_bounds__(512) void out_kernel(float* __restrict__ out) {
    extern __shared__ __align__(16) char sm[];
    const uint32_t sb = smem_u32(sm);

    const int tid  = threadIdx.x;
    const int wid  = tid >> 5;
    const int lane = tid & 31;
    const int qt = (NTILES - 1) - blockIdx.x;        // longest blocks first
    const int b  = blockIdx.y;
    const int q0 = qt * 64;
    const int wm = wid >> 2;         // q-group (16 rows)
    const int wk = wid & 3;          // k-quarter (16 cols)

    // Stage issue: K,V hi/lo tiles [64k][64h]
    auto issue_tile = [&](int kt, int s) {
        const int k0 = kt * 64;
#pragma unroll
        for (int l = 0; l < 4; l++) {
            int idx = tid + l * 512;
            int arr = idx >> 9;                      // 0:KH 1:KL 2:VH 3:VL
            int w = idx & 511, r = w >> 3, u = w & 7;
            const __nv_bfloat16* src =
                (arr == 0) ? g_kh + (size_t)(b * NT + k0 + r) * NH + u * 8 :
                (arr == 1) ? g_kl + (size_t)(b * NT + k0 + r) * NH + u * 8 :
                (arr == 2) ? g_vh + (size_t)(b * NT + k0 + r) * NH + u * 8 :
                             g_vl + (size_t)(b * NT + k0 + r) * NH + u * 8;
            cp_async16(sb + OSTG(s) + arr * 8192 + swz128(r, u), src);
        }
        CP_COMMIT();
    };

    issue_tile(0, 0);

    // Q tile -> smem (hi/lo), plain LDG->STS
#pragma unroll
    for (int l = 0; l < 2; l++) {
        int idx = tid + l * 512;
        int hilo = idx >> 9;
        int w = idx & 511, r = w >> 3, u = w & 7;
        const __nv_bfloat16* src = (hilo ? g_ql : g_qh) + (size_t)(b * NT + q0 + r) * NH + u * 8;
        *(uint4*)(sm + (hilo ? OQL : OQH) + swz128(r, u)) = *(const uint4*)src;
    }
    __syncthreads();

    // Hoisted Q A-frags (loop-invariant): 4 h-k16-steps x hi/lo
    uint32_t qfh[4][4], qfl[4][4];
    {
        int rA = wm * 16 + (lane & 15);
#pragma unroll
        for (int ks = 0; ks < 4; ks++) {
            int uA = 2 * ks + (lane >> 4);
            LDSM_X4(qfh[ks][0], qfh[ks][1], qfh[ks][2], qfh[ks][3], sb + OQH + swz128(rA, uA));
            LDSM_X4(qfl[ks][0], qfl[ks][1], qfl[ks][2], qfl[ks][3], sb + OQL + swz128(rA, uA));
        }
    }

    float acc[8][4];
#pragma unroll
    for (int nh = 0; nh < 8; nh++)
#pragma unroll
        for (int r = 0; r < 4; r++) acc[nh][r] = 0.f;

    const float* rv = g_rinv + b * NT;
    const int qwlo = q0 + wm * 16;       // warp's lowest q row

    for (int kt = 0; kt <= qt; kt++) {
        const int s = kt & 1;
        if (kt < qt) { issue_tile(kt + 1, s ^ 1); CP_WAIT(1); }
        else         { CP_WAIT(0); }
        __syncthreads();                 // stage s ready

        const int kb = kt * 64 + wk * 16;    // warp's k-quarter base
        if (kb <= qwlo + 15) {               // else: fully masked -> skip
            const uint32_t KH = sb + OSTG(s);
            const uint32_t KL = KH + 8192;
            const uint32_t VH = KH + 16384;
            const uint32_t VL = KH + 24576;

            // S = Q.K^T for this warp's 16q x 16k block (2 k-n8 tiles)
            float sacc[2][4];
#pragma unroll
            for (int ni = 0; ni < 2; ni++)
#pragma unroll
                for (int r = 0; r < 4; r++) sacc[ni][r] = 0.f;

#pragma unroll
            for (int ks = 0; ks < 4; ks++) {
#pragma unroll
                for (int ni = 0; ni < 2; ni++) {
                    int rB = wk * 16 + ni * 8 + (lane & 7);
                    int u = 2 * ks + ((lane >> 3) & 1);
                    uint32_t bh[2], bl[2];
                    LDSM_X2(bh[0], bh[1], KH + swz128(rB, u));
                    LDSM_X2(bl[0], bl[1], KL + swz128(rB, u));
                    MMA_BF16(sacc[ni], qfh[ks], bh);
                    MMA_BF16(sacc[ni], qfh[ks], bl);
                    MMA_BF16(sacc[ni], qfl[ks], bh);
                }
            }

            // exp * rinv + mask, pack D-frags into P A-frags (hi/lo)
            const bool full = (kb + 15 <= qwlo);
            const int qgA = qwlo + (lane >> 2);
            uint32_t pah[4], pal[4];
#pragma unroll
            for (int ni = 0; ni < 2; ni++) {
                int kg = kb + ni * 8 + 2 * (lane & 3);
                float2 rvv = *(const float2*)(rv + kg);
                float e0 = (full || qgA     >= kg    ) ? __expf(sacc[ni][0] * SCALE) * rvv.x : 0.f;
                float e1 = (full || qgA     >= kg + 1) ? __expf(sacc[ni][1] * SCALE) * rvv.y : 0.f;
                float e2 = (full || qgA + 8 >= kg    ) ? __expf(sacc[ni][2] * SCALE) * rvv.x : 0.f;
                float e3 = (full || qgA + 8 >= kg + 1) ? __expf(sacc[ni][3] * SCALE) * rvv.y : 0.f;
                __nv_bfloat16 h0, l0, h1, l1, h2, l2, h3, l3;
                bf16split(e0, h0, l0); bf16split(e1, h1, l1);
                bf16split(e2, h2, l2); bf16split(e3, h3, l3);
                pah[ni * 2 + 0] = packbf(h0, h1); pah[ni * 2 + 1] = packbf(h2, h3);
                pal[ni * 2 + 0] = packbf(l0, l1); pal[ni * 2 + 1] = packbf(l2, l3);
            }

            // out += P @ V  (contraction = warp's 16k; 8 h-n8 tiles)
            int rB = wk * 16 + (lane & 7) + 8 * ((lane >> 3) & 1);
#pragma unroll
            for (int nh = 0; nh < 8; nh++) {
                uint32_t vh[2], vl[2];
                LDSM_X2_T(vh[0], vh[1], VH + swz128(rB, nh));
                LDSM_X2_T(vl[0], vl[1], VL + swz128(rB, nh));
                MMA_BF16(acc[nh], pah, vh);
                MMA_BF16(acc[nh], pah, vl);
                MMA_BF16(acc[nh], pal, vh);
            }
        }
        __syncthreads();                 // done reading stage s before reuse
    }

    // Reduce over k-quarters: wk=1..3 store to 3 smem buffers (stride 68
    // floats, stage area is dead), wk=0 adds and writes out.
    float* red = (float*)(sm + ORED);
    if (wk) {
        float* buf = red + (wk - 1) * 4352;          // 68*64 floats
#pragma unroll
        for (int nh = 0; nh < 8; nh++) {
            int h = nh * 8 + 2 * (lane & 3);
            int row = wm * 16 + (lane >> 2);
            buf[row * 68 + h]       = acc[nh][0];
            buf[row * 68 + h + 1]   = acc[nh][1];
            buf[(row + 8) * 68 + h]     = acc[nh][2];
            buf[(row + 8) * 68 + h + 1] = acc[nh][3];
        }
    }
    __syncthreads();
    if (wk == 0) {
#pragma unroll
        for (int nh = 0; nh < 8; nh++) {
            int h = nh * 8 + 2 * (lane & 3);
            int row = wm * 16 + (lane >> 2);
            float2 v0, v1;
            v0.x = acc[nh][0] + red[row * 68 + h]     + red[4352 + row * 68 + h]     + red[8704 + row * 68 + h];
            v0.y = acc[nh][1] + red[row * 68 + h + 1] + red[4352 + row * 68 + h + 1] + red[8704 + row * 68 + h + 1];
            v1.x = acc[nh][2] + red[(row + 8) * 68 + h]     + red[4352 + (row + 8) * 68 + h]     + red[8704 + (row + 8) * 68 + h];
            v1.y = acc[nh][3] + red[(row + 8) * 68 + h + 1] + red[4352 + (row + 8) * 68 + h + 1] + red[8704 + (row + 8) * 68 + h + 1];
            *(float2*)(out + (size_t)(b * NT + q0 + row) * NH + h) = v0;
            *(float2*)(out + (size_t)(b * NT + q0 + row + 8) * NH + h) = v1;
        }
    }
}

// ---------------------------------------------------------------------------
// Launch (graph-capturable, allocation-free, atomic-free -> deterministic).
// Input order per metadata: x, Wk, Wq, Wv.
// ---------------------------------------------------------------------------
extern "C" void kernel_launch(void* const* d_in, const int* in_sizes, int n_in,
                              void* d_out, int out_size) {
    const float* x  = (const float*)d_in[0];
    const float* Wk = (const float*)d_in[1];
    const float* Wq = (const float*)d_in[2];
    const float* Wv = (const float*)d_in[3];
    float* out = (float*)d_out;

    cudaFuncSetAttribute(projmma_kernel,
                         cudaFuncAttributeMaxDynamicSharedMemorySize, PJ_SMEM);
    cudaFuncSetAttribute(out_kernel,
                         cudaFuncAttributeMaxDynamicSharedMemorySize, OUT_SMEM);

    wconv_kernel<<<48, 256>>>(Wq, Wk, Wv);
    projmma_kernel<<<(NB * NT) / 128, 256, PJ_SMEM>>>(x);
    colsum_kernel<<<dim3(KT128, QCHUNK, NB), 256>>>();
    rinv_kernel<<<(NB * NT) / 256, 256>>>();
    out_kernel<<<dim3(NTILES, NB), 512, OUT_SMEM>>>(out);
}

// round 16
// speedup vs baseline: 1.5969x; 1.1365x over previous
#include <cuda_runtime.h>
#include <cuda_bf16.h>
#include <math.h>
#include <stdint.h>

// Problem constants
#define NB 8
#define NT 2048
#define ND 1024
#define NH 64
#define SCALE 0.125f            // H^-0.5 = 1/8
#define NTILES (NT / 64)        // 32 q-tiles (64 rows)
#define KT128  (NT / 128)       // 16 k-tiles (128 cols) for colsum
#define QCHUNK 4                // q-chunks per k-tile (8 q-tiles each)

// Scratch (allocation-free: __device__ globals)
__device__ float g_part[QCHUNK * NB * NT];             // partial column sums
__device__ float g_rinv[NB * NT];                      // 1 / colsum
__device__ __nv_bfloat16 g_qh[NB * NT * NH];           // Q hi/lo bf16
__device__ __nv_bfloat16 g_ql[NB * NT * NH];
__device__ __nv_bfloat16 g_kh[NB * NT * NH];           // K hi/lo bf16
__device__ __nv_bfloat16 g_kl[NB * NT * NH];
__device__ __nv_bfloat16 g_vh[NB * NT * NH];           // V hi/lo bf16
__device__ __nv_bfloat16 g_vl[NB * NT * NH];
// W transposed + split: [hilo][mat][n=64][k=1024] bf16
__device__ __nv_bfloat16 g_wb[2 * 3 * 64 * 1024];

// ---------------------------------------------------------------------------
// Helpers: legacy tensor path (compute_103-legal): ldmatrix + mma.sync bf16,
// plus cp.async (Ampere+) for async gmem->smem pipelines.
// ---------------------------------------------------------------------------
__device__ __forceinline__ uint32_t smem_u32(const void* p) {
    uint32_t a;
    asm("{ .reg .u64 t; cvta.to.shared.u64 t, %1; cvt.u32.u64 %0, t; }"
        : "=r"(a) : "l"(p));
    return a;
}
#define LDSM_X4(r0, r1, r2, r3, a)                                              \
    asm volatile("ldmatrix.sync.aligned.m8n8.x4.shared.b16 {%0,%1,%2,%3}, [%4];" \
                 : "=r"(r0), "=r"(r1), "=r"(r2), "=r"(r3) : "r"(a))
#define LDSM_X2(r0, r1, a)                                                      \
    asm volatile("ldmatrix.sync.aligned.m8n8.x2.shared.b16 {%0,%1}, [%2];"      \
                 : "=r"(r0), "=r"(r1) : "r"(a))
#define LDSM_X2_T(r0, r1, a)                                                    \
    asm volatile("ldmatrix.sync.aligned.m8n8.x2.trans.shared.b16 {%0,%1}, [%2];" \
                 : "=r"(r0), "=r"(r1) : "r"(a))
#define MMA_BF16(d, a, b)                                                       \
    asm volatile("mma.sync.aligned.m16n8k16.row.col.f32.bf16.bf16.f32 "         \
                 "{%0,%1,%2,%3}, {%4,%5,%6,%7}, {%8,%9}, {%0,%1,%2,%3};"        \
                 : "+f"((d)[0]), "+f"((d)[1]), "+f"((d)[2]), "+f"((d)[3])       \
                 : "r"((a)[0]), "r"((a)[1]), "r"((a)[2]), "r"((a)[3]),          \
                   "r"((b)[0]), "r"((b)[1]))

__device__ __forceinline__ void cp_async16(uint32_t smem, const void* g) {
    asm volatile("cp.async.cg.shared.global [%0], [%1], 16;"
                 :: "r"(smem), "l"(g) : "memory");
}
#define CP_COMMIT() asm volatile("cp.async.commit_group;" ::: "memory")
#define CP_WAIT(N)  asm volatile("cp.async.wait_group " #N ";" ::: "memory")

// Swizzles (16B units). 64B rows (proj) / 128B rows (colsum, out).
__device__ __forceinline__ uint32_t swzA(int r, int u) {
    return (uint32_t)(r * 64 + ((u ^ ((r >> 1) & 3)) << 4));
}
__device__ __forceinline__ uint32_t swz128(int r, int u) {
    return (uint32_t)(r * 128 + ((u ^ (r & 7)) << 4));
}
__device__ __forceinline__ void bf16split(float f, __nv_bfloat16& h, __nv_bfloat16& l) {
    h = __float2bfloat16_rn(f);
    l = __float2bfloat16_rn(f - __bfloat162float(h));
}
__device__ __forceinline__ uint32_t packbf(__nv_bfloat16 a, __nv_bfloat16 b) {
    __nv_bfloat162 t; t.x = a; t.y = b;
    return *(uint32_t*)&t;
}

// ---------------------------------------------------------------------------
// Kernel 0: W -> transposed, bf16 hi/lo split, B layout [hilo][mat][n][k].
// ---------------------------------------------------------------------------
__global__ __launch_bounds__(256) void wconv_kernel(
    const float* __restrict__ Wq, const float* __restrict__ Wk,
    const float* __restrict__ Wv)
{
    __shared__ float tile[64 * 65];
    const int mat = blockIdx.x >> 4;
    const int k0  = (blockIdx.x & 15) * 64;
    const float* W = (mat == 0) ? Wq : (mat == 1) ? Wk : Wv;
    const int tid = threadIdx.x;

#pragma unroll
    for (int l = 0; l < 16; l++) {
        int idx = tid + l * 256;
        int k = idx >> 6, n = idx & 63;
        tile[k * 65 + n] = W[(k0 + k) * NH + n];
    }
    __syncthreads();
#pragma unroll
    for (int l = 0; l < 16; l++) {
        int idx = tid + l * 256;
        int n = idx >> 6, k = idx & 63;
        __nv_bfloat16 h, lo;
        bf16split(tile[k * 65 + n], h, lo);
        g_wb[((0 * 3 + mat) * 64 + n) * 1024 + k0 + k] = h;
        g_wb[((1 * 3 + mat) * 64 + n) * 1024 + k0 + k] = lo;
    }
}

// ---------------------------------------------------------------------------
// Kernel 1: projection GEMM via mma.sync bf16, split-fp32 (3 terms).
// Pipelined (cp.async B, reg-prefetch A). q,k,v all emitted as bf16 hi/lo.
// ---------------------------------------------------------------------------
#define PJ_ALO 8192
#define PJ_B(s) (16384 + (s) * 24576)
#define PJ_SMEM 65536

__global__ __launch_bounds__(256) void projmma_kernel(const float* __restrict__ x)
{
    extern __shared__ __align__(16) char sm[];
    const uint32_t sb = smem_u32(sm);

    const int tid  = threadIdx.x;
    const int wid  = tid >> 5;
    const int lane = tid & 31;
    const int row0 = blockIdx.x * 128;
    const int r0w  = (wid >> 1) * 32;
    const int c0w  = (wid & 1) * 96;

    float acc[2][12][4];
#pragma unroll
    for (int mi = 0; mi < 2; mi++)
#pragma unroll
        for (int ni = 0; ni < 12; ni++)
#pragma unroll
            for (int r = 0; r < 4; r++) acc[mi][ni][r] = 0.f;

    const int rA0 = r0w + (lane & 15);
    const int uHiA = lane >> 4;
    const int ldRow = (tid >> 3);
    const int ldKf  = (tid & 7) * 4;

    const char* bSrcBase[6];
    uint32_t bDstOff[6];
#pragma unroll
    for (int l = 0; l < 6; l++) {
        int idx = tid + l * 256;
        int rowhl = idx >> 2;
        int seg = idx & 3;
        int hilo = rowhl >= 192;
        int row = rowhl - hilo * 192;
        bSrcBase[l] = (const char*)g_wb + (size_t)rowhl * 2048 + seg * 16;
        bDstOff[l] = (uint32_t)(hilo * 12288) + swzA(row, seg);
    }

    float4 xv[4];
#pragma unroll
    for (int l = 0; l < 4; l++)
        xv[l] = *(const float4*)(x + (size_t)(row0 + ldRow + l * 32) * ND + 0 + ldKf);
#pragma unroll
    for (int l = 0; l < 6; l++)
        cp_async16(sb + PJ_B(0) + bDstOff[l], bSrcBase[l]);
    CP_COMMIT();

    for (int c = 0; c < 32; c++) {
        const int s = c & 1;
        __syncthreads();
#pragma unroll
        for (int l = 0; l < 4; l++) {
            int row = ldRow + l * 32;
            __nv_bfloat162 h01, h23, l01, l23;
            bf16split(xv[l].x, h01.x, l01.x); bf16split(xv[l].y, h01.y, l01.y);
            bf16split(xv[l].z, h23.x, l23.x); bf16split(xv[l].w, h23.y, l23.y);
            uint32_t off = swzA(row, ldKf >> 3) + ((ldKf & 4) ? 8 : 0);
            uint2 hv = { *(uint32_t*)&h01, *(uint32_t*)&h23 };
            uint2 lv = { *(uint32_t*)&l01, *(uint32_t*)&l23 };
            *(uint2*)(sm + off) = hv;
            *(uint2*)(sm + PJ_ALO + off) = lv;
        }
        if (c < 31) {
#pragma unroll
            for (int l = 0; l < 6; l++)
                cp_async16(sb + PJ_B(s ^ 1) + bDstOff[l],
                           bSrcBase[l] + (size_t)(c + 1) * 64);
            CP_COMMIT();
            CP_WAIT(1);
        } else {
            CP_WAIT(0);
        }
        __syncthreads();
        if (c < 31) {
#pragma unroll
            for (int l = 0; l < 4; l++)
                xv[l] = *(const float4*)(x + (size_t)(row0 + ldRow + l * 32) * ND
                                           + (c + 1) * 32 + ldKf);
        }

        const uint32_t bSt = sb + PJ_B(s);
#pragma unroll
        for (int st = 0; st < 2; st++) {
            uint32_t ah[2][4], al[2][4];
#pragma unroll
            for (int mi = 0; mi < 2; mi++) {
                int r = rA0 + mi * 16;
                uint32_t off = swzA(r, 2 * st + uHiA);
                LDSM_X4(ah[mi][0], ah[mi][1], ah[mi][2], ah[mi][3], sb + off);
                LDSM_X4(al[mi][0], al[mi][1], al[mi][2], al[mi][3], sb + PJ_ALO + off);
            }
#pragma unroll
            for (int ni = 0; ni < 12; ni++) {
                int rB = c0w + ni * 8 + (lane & 7);
                uint32_t off = swzA(rB, 2 * st + ((lane >> 3) & 1));
                uint32_t bh[2], bl[2];
                LDSM_X2(bh[0], bh[1], bSt + off);
                LDSM_X2(bl[0], bl[1], bSt + 12288 + off);
#pragma unroll
                for (int mi = 0; mi < 2; mi++) {
                    MMA_BF16(acc[mi][ni], ah[mi], bh);
                    MMA_BF16(acc[mi][ni], ah[mi], bl);
                    MMA_BF16(acc[mi][ni], al[mi], bh);
                }
            }
        }
    }

    // Epilogue: q,k,v all -> bf16 hi/lo
#pragma unroll
    for (int ni = 0; ni < 12; ni++) {
        int cg = c0w + ni * 8 + (lane & 3) * 2;
        int h = cg & 63;
        __nv_bfloat16* dh = (cg < 64) ? g_qh : (cg < 128) ? g_kh : g_vh;
        __nv_bfloat16* dl = (cg < 64) ? g_ql : (cg < 128) ? g_kl : g_vl;
#pragma unroll
        for (int mi = 0; mi < 2; mi++) {
            int r = row0 + r0w + mi * 16 + (lane >> 2);
            __nv_bfloat162 h2, l2;
            bf16split(acc[mi][ni][0], h2.x, l2.x);
            bf16split(acc[mi][ni][1], h2.y, l2.y);
            *(__nv_bfloat162*)(dh + (size_t)r * NH + h) = h2;
            *(__nv_bfloat162*)(dl + (size_t)r * NH + h) = l2;
            bf16split(acc[mi][ni][2], h2.x, l2.x);
            bf16split(acc[mi][ni][3], h2.y, l2.y);
            *(__nv_bfloat162*)(dh + (size_t)(r + 8) * NH + h) = h2;
            *(__nv_bfloat162*)(dl + (size_t)(r + 8) * NH + h) = l2;
        }
    }
}

// ---------------------------------------------------------------------------
// Kernel 2: colsum via HMMA (epilogue = mask/exp/csum only; no P stores).
// ---------------------------------------------------------------------------
#define CS_KH 0
#define CS_KL 16384
#define CS_QH 32768
#define CS_QL 40960
#define CS_RED 32768

__global__ __launch_bounds__(256) void colsum_kernel() {
    __shared__ __align__(16) char sm[49152];
    const uint32_t sb = smem_u32(sm);

    const int tid  = threadIdx.x;
    const int wid  = tid >> 5;
    const int lane = tid & 31;
    const int kt = blockIdx.x;
    const int c  = blockIdx.y;
    const int b  = blockIdx.z;
    const int k0 = kt * 128;
    const int wm = wid & 3;
    const int wn = wid >> 2;

    int qt_begin = 2 * kt; if (8 * c > qt_begin) qt_begin = 8 * c;
    const int qt_end = 8 * c + 8;

    if (qt_begin >= qt_end) {
        if (tid < 128) g_part[(c * NB + b) * NT + k0 + tid] = 0.f;
        return;
    }

#pragma unroll
    for (int l = 0; l < 8; l++) {
        int idx = tid + l * 256;
        int hilo = idx >> 10;
        int w = idx & 1023, r = w >> 3, u = w & 7;
        const __nv_bfloat16* src = (hilo ? g_kl : g_kh) + (size_t)(b * NT + k0 + r) * NH + u * 8;
        *(uint4*)(sm + (hilo ? CS_KL : CS_KH) + swz128(r, u)) = *(const uint4*)src;
    }

    float csum[4] = {0.f, 0.f, 0.f, 0.f};

    uint4 qreg[4];
    {
        const int q0 = qt_begin * 64;
#pragma unroll
        for (int l = 0; l < 4; l++) {
            int idx = tid + l * 256;
            int hilo = idx >> 9;
            int w = idx & 511, r = w >> 3, u = w & 7;
            const __nv_bfloat16* src = (hilo ? g_ql : g_qh) + (size_t)(b * NT + q0 + r) * NH + u * 8;
            qreg[l] = *(const uint4*)src;
        }
    }

    for (int qt = qt_begin; qt < qt_end; qt++) {
        const int q0 = qt * 64;
        __syncthreads();
#pragma unroll
        for (int l = 0; l < 4; l++) {
            int idx = tid + l * 256;
            int hilo = idx >> 9;
            int w = idx & 511, r = w >> 3, u = w & 7;
            *(uint4*)(sm + (hilo ? CS_QL : CS_QH) + swz128(r, u)) = qreg[l];
        }
        __syncthreads();
        if (qt + 1 < qt_end) {
            const int q1 = (qt + 1) * 64;
#pragma unroll
            for (int l = 0; l < 4; l++) {
                int idx = tid + l * 256;
                int hilo = idx >> 9;
                int w = idx & 511, r = w >> 3, u = w & 7;
                const __nv_bfloat16* src = (hilo ? g_ql : g_qh) + (size_t)(b * NT + q1 + r) * NH + u * 8;
                qreg[l] = *(const uint4*)src;
            }
        }

        float acc[2][4][4];
#pragma unroll
        for (int mi = 0; mi < 2; mi++)
#pragma unroll
            for (int ni = 0; ni < 4; ni++)
#pragma unroll
                for (int r = 0; r < 4; r++) acc[mi][ni][r] = 0.f;

#pragma unroll
        for (int s = 0; s < 4; s++) {
            uint32_t ah[2][4], al[2][4];
#pragma unroll
            for (int mi = 0; mi < 2; mi++) {
                int r = wm * 32 + mi * 16 + (lane & 15);
                int u = 2 * s + (lane >> 4);
                LDSM_X4(ah[mi][0], ah[mi][1], ah[mi][2], ah[mi][3], sb + CS_KH + swz128(r, u));
                LDSM_X4(al[mi][0], al[mi][1], al[mi][2], al[mi][3], sb + CS_KL + swz128(r, u));
            }
#pragma unroll
            for (int ni = 0; ni < 4; ni++) {
                int rB = wn * 32 + ni * 8 + (lane & 7);
                int u = 2 * s + ((lane >> 3) & 1);
                uint32_t bh[2], bl[2];
                LDSM_X2(bh[0], bh[1], sb + CS_QH + swz128(rB, u));
                LDSM_X2(bl[0], bl[1], sb + CS_QL + swz128(rB, u));
#pragma unroll
                for (int mi = 0; mi < 2; mi++) {
                    MMA_BF16(acc[mi][ni], ah[mi], bh);
                    MMA_BF16(acc[mi][ni], ah[mi], bl);
                    MMA_BF16(acc[mi][ni], al[mi], bh);
                }
            }
        }

        const bool full = (q0 >= k0 + 128);
#pragma unroll
        for (int mi = 0; mi < 2; mi++) {
#pragma unroll
            for (int ni = 0; ni < 4; ni++) {
                int qg = q0 + wn * 32 + ni * 8 + 2 * (lane & 3);
#pragma unroll
                for (int half = 0; half < 2; half++) {
                    int kg = k0 + wm * 32 + mi * 16 + (lane >> 2) + 8 * half;
                    float d0 = acc[mi][ni][2 * half];
                    float d1 = acc[mi][ni][2 * half + 1];
                    float e0 = (full || qg >= kg) ? __expf(d0 * SCALE) : 0.f;
                    float e1 = (full || qg + 1 >= kg) ? __expf(d1 * SCALE) : 0.f;
                    csum[mi * 2 + half] += e0 + e1;
                }
            }
        }
    }

#pragma unroll
    for (int i = 0; i < 4; i++) {
        csum[i] += __shfl_xor_sync(0xFFFFFFFF, csum[i], 1);
        csum[i] += __shfl_xor_sync(0xFFFFFFFF, csum[i], 2);
    }
    __syncthreads();
    float* red = (float*)(sm + CS_RED);
    if ((lane & 3) == 0) {
#pragma unroll
        for (int mi = 0; mi < 2; mi++)
#pragma unroll
            for (int half = 0; half < 2; half++)
                red[wn * 128 + wm * 32 + mi * 16 + (lane >> 2) + 8 * half] = csum[mi * 2 + half];
    }
    __syncthreads();
    if (tid < 128)
        g_part[(c * NB + b) * NT + k0 + tid] = red[tid] + red[128 + tid];
}

// ---------------------------------------------------------------------------
// Kernel 3: rinv[b][k] = 1 / sum of partial column sums
// ---------------------------------------------------------------------------
__global__ __launch_bounds__(256) void rinv_kernel() {
    int gid = blockIdx.x * 256 + threadIdx.x;        // NB*NT = 16384
    int b = gid >> 11, k = gid & 2047;
    float s = g_part[(0 * NB + b) * NT + k] + g_part[(1 * NB + b) * NT + k]
            + g_part[(2 * NB + b) * NT + k] + g_part[(3 * NB + b) * NT + k];
    g_rinv[gid] = 1.f / s;
}

// ---------------------------------------------------------------------------
// Kernel 4: fused out, UNIFORM paired scheduling: CTA = (pair, b) processes
// q-tiles pair AND 31-pair sequentially -> every CTA does exactly 33 k-tile
// steps (no triangular imbalance under co-residency). Body identical to R15:
// S via HMMA, exp*rinv+mask in regs (D-frag==A-frag trick), P@V via HMMA.
// 512 threads: warps = 4 q-groups (16q) x 4 k-quarters (16k).
// smem 80KB: QH 8K | QL 8K | stage{0,1}: KH 8K KL 8K VH 8K VL 8K.
// ---------------------------------------------------------------------------
#define OQH 0
#define OQL 8192
#define OSTG(s) (16384 + (s) * 32768)
#define ORED OSTG(0)             // reduction reuses dead stage area
#define OUT_SMEM 81920

__global__ __launch_bounds__(512) void out_kernel(float* __restrict__ out) {
    extern __shared__ __align__(16) char sm[];
    const uint32_t sb = smem_u32(sm);

    const int tid  = threadIdx.x;
    const int wid  = tid >> 5;
    const int lane = tid & 31;
    const int pair = blockIdx.x;     // 0..15
    const int b    = blockIdx.y;
    const int wm = wid >> 2;         // q-group (16 rows)
    const int wk = wid & 3;          // k-quarter (16 cols)

    auto issue_tile = [&](int kt, int s) {
        const int k0 = kt * 64;
#pragma unroll
        for (int l = 0; l < 4; l++) {
            int idx = tid + l * 512;
            int arr = idx >> 9;                      // 0:KH 1:KL 2:VH 3:VL
            int w = idx & 511, r = w >> 3, u = w & 7;
            const __nv_bfloat16* src =
                (arr == 0) ? g_kh + (size_t)(b * NT + k0 + r) * NH + u * 8 :
                (arr == 1) ? g_kl + (size_t)(b * NT + k0 + r) * NH + u * 8 :
                (arr == 2) ? g_vh + (size_t)(b * NT + k0 + r) * NH + u * 8 :
                             g_vl + (size_t)(b * NT + k0 + r) * NH + u * 8;
            cp_async16(sb + OSTG(s) + arr * 8192 + swz128(r, u), src);
        }
        CP_COMMIT();
    };

    const float* rv = g_rinv + b * NT;

    for (int ph = 0; ph < 2; ph++) {
        const int qt = ph ? (NTILES - 1 - pair) : pair;
        const int q0 = qt * 64;

        if (ph) __syncthreads();     // phase-0 reduction reads done before
                                     // stage area (aliases red) is re-issued
        issue_tile(0, 0);

        // Q tile -> smem (hi/lo)
#pragma unroll
        for (int l = 0; l < 2; l++) {
            int idx = tid + l * 512;
            int hilo = idx >> 9;
            int w = idx & 511, r = w >> 3, u = w & 7;
            const __nv_bfloat16* src = (hilo ? g_ql : g_qh) + (size_t)(b * NT + q0 + r) * NH + u * 8;
            *(uint4*)(sm + (hilo ? OQL : OQH) + swz128(r, u)) = *(const uint4*)src;
        }
        __syncthreads();

        // Hoisted Q A-frags (loop-invariant): 4 h-k16-steps x hi/lo
        uint32_t qfh[4][4], qfl[4][4];
        {
            int rA = wm * 16 + (lane & 15);
#pragma unroll
            for (int ks = 0; ks < 4; ks++) {
                int uA = 2 * ks + (lane >> 4);
                LDSM_X4(qfh[ks][0], qfh[ks][1], qfh[ks][2], qfh[ks][3], sb + OQH + swz128(rA, uA));
                LDSM_X4(qfl[ks][0], qfl[ks][1], qfl[ks][2], qfl[ks][3], sb + OQL + swz128(rA, uA));
            }
        }

        float acc[8][4];
#pragma unroll
        for (int nh = 0; nh < 8; nh++)
#pragma unroll
            for (int r = 0; r < 4; r++) acc[nh][r] = 0.f;

        const int qwlo = q0 + wm * 16;

        for (int kt = 0; kt <= qt; kt++) {
            const int s = kt & 1;
            if (kt < qt) { issue_tile(kt + 1, s ^ 1); CP_WAIT(1); }
            else         { CP_WAIT(0); }
            __syncthreads();             // stage s ready

            const int kb = kt * 64 + wk * 16;
            if (kb <= qwlo + 15) {       // else fully masked -> skip
                const uint32_t KH = sb + OSTG(s);
                const uint32_t KL = KH + 8192;
                const uint32_t VH = KH + 16384;
                const uint32_t VL = KH + 24576;

                float sacc[2][4];
#pragma unroll
                for (int ni = 0; ni < 2; ni++)
#pragma unroll
                    for (int r = 0; r < 4; r++) sacc[ni][r] = 0.f;

#pragma unroll
                for (int ks = 0; ks < 4; ks++) {
#pragma unroll
                    for (int ni = 0; ni < 2; ni++) {
                        int rB = wk * 16 + ni * 8 + (lane & 7);
                        int u = 2 * ks + ((lane >> 3) & 1);
                        uint32_t bh[2], bl[2];
                        LDSM_X2(bh[0], bh[1], KH + swz128(rB, u));
                        LDSM_X2(bl[0], bl[1], KL + swz128(rB, u));
                        MMA_BF16(sacc[ni], qfh[ks], bh);
                        MMA_BF16(sacc[ni], qfh[ks], bl);
                        MMA_BF16(sacc[ni], qfl[ks], bh);
                    }
                }

                const bool full = (kb + 15 <= qwlo);
                const int qgA = qwlo + (lane >> 2);
                uint32_t pah[4], pal[4];
#pragma unroll
                for (int ni = 0; ni < 2; ni++) {
                    int kg = kb + ni * 8 + 2 * (lane & 3);
                    float2 rvv = *(const float2*)(rv + kg);
                    float e0 = (full || qgA     >= kg    ) ? __expf(sacc[ni][0] * SCALE) * rvv.x : 0.f;
                    float e1 = (full || qgA     >= kg + 1) ? __expf(sacc[ni][1] * SCALE) * rvv.y : 0.f;
                    float e2 = (full || qgA + 8 >= kg    ) ? __expf(sacc[ni][2] * SCALE) * rvv.x : 0.f;
                    float e3 = (full || qgA + 8 >= kg + 1) ? __expf(sacc[ni][3] * SCALE) * rvv.y : 0.f;
                    __nv_bfloat16 h0, l0, h1, l1, h2, l2, h3, l3;
                    bf16split(e0, h0, l0); bf16split(e1, h1, l1);
                    bf16split(e2, h2, l2); bf16split(e3, h3, l3);
                    pah[ni * 2 + 0] = packbf(h0, h1); pah[ni * 2 + 1] = packbf(h2, h3);
                    pal[ni * 2 + 0] = packbf(l0, l1); pal[ni * 2 + 1] = packbf(l2, l3);
                }

                int rB = wk * 16 + (lane & 7) + 8 * ((lane >> 3) & 1);
#pragma unroll
                for (int nh = 0; nh < 8; nh++) {
                    uint32_t vh[2], vl[2];
                    LDSM_X2_T(vh[0], vh[1], VH + swz128(rB, nh));
                    LDSM_X2_T(vl[0], vl[1], VL + swz128(rB, nh));
                    MMA_BF16(acc[nh], pah, vh);
                    MMA_BF16(acc[nh], pah, vl);
                    MMA_BF16(acc[nh], pal, vh);
                }
            }
            __syncthreads();             // done reading stage s before reuse
        }

        // Reduce over k-quarters: wk=1..3 -> 3 smem buffers, wk=0 adds+writes.
        float* red = (float*)(sm + ORED);
        if (wk) {
            float* buf = red + (wk - 1) * 4352;      // 68*64 floats
#pragma unroll
            for (int nh = 0; nh < 8; nh++) {
                int h = nh * 8 + 2 * (lane & 3);
                int row = wm * 16 + (lane >> 2);
                buf[row * 68 + h]       = acc[nh][0];
                buf[row * 68 + h + 1]   = acc[nh][1];
                buf[(row + 8) * 68 + h]     = acc[nh][2];
                buf[(row + 8) * 68 + h + 1] = acc[nh][3];
            }
        }
        __syncthreads();
        if (wk == 0) {
#pragma unroll
            for (int nh = 0; nh < 8; nh++) {
                int h = nh * 8 + 2 * (lane & 3);
                int row = wm * 16 + (lane >> 2);
                float2 v0, v1;
                v0.x = acc[nh][0] + red[row * 68 + h]     + red[4352 + row * 68 + h]     + red[8704 + row * 68 + h];
                v0.y = acc[nh][1] + red[row * 68 + h + 1] + red[4352 + row * 68 + h + 1] + red[8704 + row * 68 + h + 1];
                v1.x = acc[nh][2] + red[(row + 8) * 68 + h]     + red[4352 + (row + 8) * 68 + h]     + red[8704 + (row + 8) * 68 + h];
                v1.y = acc[nh][3] + red[(row + 8) * 68 + h + 1] + red[4352 + (row + 8) * 68 + h + 1] + red[8704 + (row + 8) * 68 + h + 1];
                *(float2*)(out + (size_t)(b * NT + q0 + row) * NH + h) = v0;
                *(float2*)(out + (size_t)(b * NT + q0 + row + 8) * NH + h) = v1;
            }
        }
    }
}

// ---------------------------------------------------------------------------
// Launch (graph-capturable, allocation-free, atomic-free -> deterministic).
// Input order per metadata: x, Wk, Wq, Wv.
// ---------------------------------------------------------------------------
extern "C" void kernel_launch(void* const* d_in, const int* in_sizes, int n_in,
                              void* d_out, int out_size) {
    const float* x  = (const float*)d_in[0];
    const float* Wk = (const float*)d_in[1];
    const float* Wq = (const float*)d_in[2];
    const float* Wv = (const float*)d_in[3];
    float* out = (float*)d_out;

    cudaFuncSetAttribute(projmma_kernel,
                         cudaFuncAttributeMaxDynamicSharedMemorySize, PJ_SMEM);
    cudaFuncSetAttribute(out_kernel,
                         cudaFuncAttributeMaxDynamicSharedMemorySize, OUT_SMEM);

    wconv_kernel<<<48, 256>>>(Wq, Wk, Wv);
    projmma_kernel<<<(NB * NT) / 128, 256, PJ_SMEM>>>(x);
    colsum_kernel<<<dim3(KT128, QCHUNK, NB), 256>>>();
    rinv_kernel<<<(NB * NT) / 256, 256>>>();
    out_kernel<<<dim3(NTILES / 2, NB), 512, OUT_SMEM>>>(out);
}

// round 17
// speedup vs baseline: 1.6009x; 1.0025x over previous
#include <cuda_runtime.h>
#include <cuda_bf16.h>
#include <math.h>
#include <stdint.h>

// Problem constants
#define NB 8
#define NT 2048
#define ND 1024
#define NH 64
#define SCALE 0.125f            // H^-0.5 = 1/8
#define NTILES (NT / 64)        // 32 q-tiles (64 rows)
#define KT128  (NT / 128)       // 16 k-tiles (128 cols) for colsum
#define QCHUNK 4                // q-chunks per k-tile (8 q-tiles each)

// Scratch (allocation-free: __device__ globals)
__device__ float g_part[QCHUNK * NB * NT];             // partial column sums
__device__ __nv_bfloat16 g_qh[NB * NT * NH];           // Q hi/lo bf16
__device__ __nv_bfloat16 g_ql[NB * NT * NH];
__device__ __nv_bfloat16 g_kh[NB * NT * NH];           // K hi/lo bf16
__device__ __nv_bfloat16 g_kl[NB * NT * NH];
__device__ __nv_bfloat16 g_vh[NB * NT * NH];           // V hi/lo bf16
__device__ __nv_bfloat16 g_vl[NB * NT * NH];
// W transposed + split: [hilo][mat][n=64][k=1024] bf16
__device__ __nv_bfloat16 g_wb[2 * 3 * 64 * 1024];

// ---------------------------------------------------------------------------
// Helpers: legacy tensor path (compute_103-legal): ldmatrix + mma.sync bf16,
// plus cp.async (Ampere+) for async gmem->smem pipelines.
// ---------------------------------------------------------------------------
__device__ __forceinline__ uint32_t smem_u32(const void* p) {
    uint32_t a;
    asm("{ .reg .u64 t; cvta.to.shared.u64 t, %1; cvt.u32.u64 %0, t; }"
        : "=r"(a) : "l"(p));
    return a;
}
#define LDSM_X4(r0, r1, r2, r3, a)                                              \
    asm volatile("ldmatrix.sync.aligned.m8n8.x4.shared.b16 {%0,%1,%2,%3}, [%4];" \
                 : "=r"(r0), "=r"(r1), "=r"(r2), "=r"(r3) : "r"(a))
#define LDSM_X2(r0, r1, a)                                                      \
    asm volatile("ldmatrix.sync.aligned.m8n8.x2.shared.b16 {%0,%1}, [%2];"      \
                 : "=r"(r0), "=r"(r1) : "r"(a))
#define LDSM_X2_T(r0, r1, a)                                                    \
    asm volatile("ldmatrix.sync.aligned.m8n8.x2.trans.shared.b16 {%0,%1}, [%2];" \
                 : "=r"(r0), "=r"(r1) : "r"(a))
#define MMA_BF16(d, a, b)                                                       \
    asm volatile("mma.sync.aligned.m16n8k16.row.col.f32.bf16.bf16.f32 "         \
                 "{%0,%1,%2,%3}, {%4,%5,%6,%7}, {%8,%9}, {%0,%1,%2,%3};"        \
                 : "+f"((d)[0]), "+f"((d)[1]), "+f"((d)[2]), "+f"((d)[3])       \
                 : "r"((a)[0]), "r"((a)[1]), "r"((a)[2]), "r"((a)[3]),          \
                   "r"((b)[0]), "r"((b)[1]))

__device__ __forceinline__ void cp_async16(uint32_t smem, const void* g) {
    asm volatile("cp.async.cg.shared.global [%0], [%1], 16;"
                 :: "r"(smem), "l"(g) : "memory");
}
#define CP_COMMIT() asm volatile("cp.async.commit_group;" ::: "memory")
#define CP_WAIT(N)  asm volatile("cp.async.wait_group " #N ";" ::: "memory")

// Swizzles (16B units). 64B rows (proj) / 128B rows (colsum, out).
__device__ __forceinline__ uint32_t swzA(int r, int u) {
    return (uint32_t)(r * 64 + ((u ^ ((r >> 1) & 3)) << 4));
}
__device__ __forceinline__ uint32_t swz128(int r, int u) {
    return (uint32_t)(r * 128 + ((u ^ (r & 7)) << 4));
}
__device__ __forceinline__ void bf16split(float f, __nv_bfloat16& h, __nv_bfloat16& l) {
    h = __float2bfloat16_rn(f);
    l = __float2bfloat16_rn(f - __bfloat162float(h));
}
__device__ __forceinline__ uint32_t packbf(__nv_bfloat16 a, __nv_bfloat16 b) {
    __nv_bfloat162 t; t.x = a; t.y = b;
    return *(uint32_t*)&t;
}

// ---------------------------------------------------------------------------
// Kernel 0: W -> transposed, bf16 hi/lo split, B layout [hilo][mat][n][k].
// ---------------------------------------------------------------------------
__global__ __launch_bounds__(256) void wconv_kernel(
    const float* __restrict__ Wq, const float* __restrict__ Wk,
    const float* __restrict__ Wv)
{
    __shared__ float tile[64 * 65];
    const int mat = blockIdx.x >> 4;
    const int k0  = (blockIdx.x & 15) * 64;
    const float* W = (mat == 0) ? Wq : (mat == 1) ? Wk : Wv;
    const int tid = threadIdx.x;

#pragma unroll
    for (int l = 0; l < 16; l++) {
        int idx = tid + l * 256;
        int k = idx >> 6, n = idx & 63;
        tile[k * 65 + n] = W[(k0 + k) * NH + n];
    }
    __syncthreads();
#pragma unroll
    for (int l = 0; l < 16; l++) {
        int idx = tid + l * 256;
        int n = idx >> 6, k = idx & 63;
        __nv_bfloat16 h, lo;
        bf16split(tile[k * 65 + n], h, lo);
        g_wb[((0 * 3 + mat) * 64 + n) * 1024 + k0 + k] = h;
        g_wb[((1 * 3 + mat) * 64 + n) * 1024 + k0 + k] = lo;
    }
}

// ---------------------------------------------------------------------------
// Kernel 1: projection GEMM via mma.sync bf16, split-fp32 (3 terms).
// Pipelined (cp.async B, reg-prefetch A). q,k,v all emitted as bf16 hi/lo.
// (unchanged from R16)
// ---------------------------------------------------------------------------
#define PJ_ALO 8192
#define PJ_B(s) (16384 + (s) * 24576)
#define PJ_SMEM 65536

__global__ __launch_bounds__(256) void projmma_kernel(const float* __restrict__ x)
{
    extern __shared__ __align__(16) char sm[];
    const uint32_t sb = smem_u32(sm);

    const int tid  = threadIdx.x;
    const int wid  = tid >> 5;
    const int lane = tid & 31;
    const int row0 = blockIdx.x * 128;
    const int r0w  = (wid >> 1) * 32;
    const int c0w  = (wid & 1) * 96;

    float acc[2][12][4];
#pragma unroll
    for (int mi = 0; mi < 2; mi++)
#pragma unroll
        for (int ni = 0; ni < 12; ni++)
#pragma unroll
            for (int r = 0; r < 4; r++) acc[mi][ni][r] = 0.f;

    const int rA0 = r0w + (lane & 15);
    const int uHiA = lane >> 4;
    const int ldRow = (tid >> 3);
    const int ldKf  = (tid & 7) * 4;

    const char* bSrcBase[6];
    uint32_t bDstOff[6];
#pragma unroll
    for (int l = 0; l < 6; l++) {
        int idx = tid + l * 256;
        int rowhl = idx >> 2;
        int seg = idx & 3;
        int hilo = rowhl >= 192;
        int row = rowhl - hilo * 192;
        bSrcBase[l] = (const char*)g_wb + (size_t)rowhl * 2048 + seg * 16;
        bDstOff[l] = (uint32_t)(hilo * 12288) + swzA(row, seg);
    }

    float4 xv[4];
#pragma unroll
    for (int l = 0; l < 4; l++)
        xv[l] = *(const float4*)(x + (size_t)(row0 + ldRow + l * 32) * ND + 0 + ldKf);
#pragma unroll
    for (int l = 0; l < 6; l++)
        cp_async16(sb + PJ_B(0) + bDstOff[l], bSrcBase[l]);
    CP_COMMIT();

    for (int c = 0; c < 32; c++) {
        const int s = c & 1;
        __syncthreads();
#pragma unroll
        for (int l = 0; l < 4; l++) {
            int row = ldRow + l * 32;
            __nv_bfloat162 h01, h23, l01, l23;
            bf16split(xv[l].x, h01.x, l01.x); bf16split(xv[l].y, h01.y, l01.y);
            bf16split(xv[l].z, h23.x, l23.x); bf16split(xv[l].w, h23.y, l23.y);
            uint32_t off = swzA(row, ldKf >> 3) + ((ldKf & 4) ? 8 : 0);
            uint2 hv = { *(uint32_t*)&h01, *(uint32_t*)&h23 };
            uint2 lv = { *(uint32_t*)&l01, *(uint32_t*)&l23 };
            *(uint2*)(sm + off) = hv;
            *(uint2*)(sm + PJ_ALO + off) = lv;
        }
        if (c < 31) {
#pragma unroll
            for (int l = 0; l < 6; l++)
                cp_async16(sb + PJ_B(s ^ 1) + bDstOff[l],
                           bSrcBase[l] + (size_t)(c + 1) * 64);
            CP_COMMIT();
            CP_WAIT(1);
        } else {
            CP_WAIT(0);
        }
        __syncthreads();
        if (c < 31) {
#pragma unroll
            for (int l = 0; l < 4; l++)
                xv[l] = *(const float4*)(x + (size_t)(row0 + ldRow + l * 32) * ND
                                           + (c + 1) * 32 + ldKf);
        }

        const uint32_t bSt = sb + PJ_B(s);
#pragma unroll
        for (int st = 0; st < 2; st++) {
            uint32_t ah[2][4], al[2][4];
#pragma unroll
            for (int mi = 0; mi < 2; mi++) {
                int r = rA0 + mi * 16;
                uint32_t off = swzA(r, 2 * st + uHiA);
                LDSM_X4(ah[mi][0], ah[mi][1], ah[mi][2], ah[mi][3], sb + off);
                LDSM_X4(al[mi][0], al[mi][1], al[mi][2], al[mi][3], sb + PJ_ALO + off);
            }
#pragma unroll
            for (int ni = 0; ni < 12; ni++) {
                int rB = c0w + ni * 8 + (lane & 7);
                uint32_t off = swzA(rB, 2 * st + ((lane >> 3) & 1));
                uint32_t bh[2], bl[2];
                LDSM_X2(bh[0], bh[1], bSt + off);
                LDSM_X2(bl[0], bl[1], bSt + 12288 + off);
#pragma unroll
                for (int mi = 0; mi < 2; mi++) {
                    MMA_BF16(acc[mi][ni], ah[mi], bh);
                    MMA_BF16(acc[mi][ni], ah[mi], bl);
                    MMA_BF16(acc[mi][ni], al[mi], bh);
                }
            }
        }
    }

    // Epilogue: q,k,v all -> bf16 hi/lo
#pragma unroll
    for (int ni = 0; ni < 12; ni++) {
        int cg = c0w + ni * 8 + (lane & 3) * 2;
        int h = cg & 63;
        __nv_bfloat16* dh = (cg < 64) ? g_qh : (cg < 128) ? g_kh : g_vh;
        __nv_bfloat16* dl = (cg < 64) ? g_ql : (cg < 128) ? g_kl : g_vl;
#pragma unroll
        for (int mi = 0; mi < 2; mi++) {
            int r = row0 + r0w + mi * 16 + (lane >> 2);
            __nv_bfloat162 h2, l2;
            bf16split(acc[mi][ni][0], h2.x, l2.x);
            bf16split(acc[mi][ni][1], h2.y, l2.y);
            *(__nv_bfloat162*)(dh + (size_t)r * NH + h) = h2;
            *(__nv_bfloat162*)(dl + (size_t)r * NH + h) = l2;
            bf16split(acc[mi][ni][2], h2.x, l2.x);
            bf16split(acc[mi][ni][3], h2.y, l2.y);
            *(__nv_bfloat162*)(dh + (size_t)(r + 8) * NH + h) = h2;
            *(__nv_bfloat162*)(dl + (size_t)(r + 8) * NH + h) = l2;
        }
    }
}

// ---------------------------------------------------------------------------
// Kernel 2: colsum via HMMA (unchanged from R16).
// ---------------------------------------------------------------------------
#define CS_KH 0
#define CS_KL 16384
#define CS_QH 32768
#define CS_QL 40960
#define CS_RED 32768

__global__ __launch_bounds__(256) void colsum_kernel() {
    __shared__ __align__(16) char sm[49152];
    const uint32_t sb = smem_u32(sm);

    const int tid  = threadIdx.x;
    const int wid  = tid >> 5;
    const int lane = tid & 31;
    const int kt = blockIdx.x;
    const int c  = blockIdx.y;
    const int b  = blockIdx.z;
    const int k0 = kt * 128;
    const int wm = wid & 3;
    const int wn = wid >> 2;

    int qt_begin = 2 * kt; if (8 * c > qt_begin) qt_begin = 8 * c;
    const int qt_end = 8 * c + 8;

    if (qt_begin >= qt_end) {
        if (tid < 128) g_part[(c * NB + b) * NT + k0 + tid] = 0.f;
        return;
    }

#pragma unroll
    for (int l = 0; l < 8; l++) {
        int idx = tid + l * 256;
        int hilo = idx >> 10;
        int w = idx & 1023, r = w >> 3, u = w & 7;
        const __nv_bfloat16* src = (hilo ? g_kl : g_kh) + (size_t)(b * NT + k0 + r) * NH + u * 8;
        *(uint4*)(sm + (hilo ? CS_KL : CS_KH) + swz128(r, u)) = *(const uint4*)src;
    }

    float csum[4] = {0.f, 0.f, 0.f, 0.f};

    uint4 qreg[4];
    {
        const int q0 = qt_begin * 64;
#pragma unroll
        for (int l = 0; l < 4; l++) {
            int idx = tid + l * 256;
            int hilo = idx >> 9;
            int w = idx & 511, r = w >> 3, u = w & 7;
            const __nv_bfloat16* src = (hilo ? g_ql : g_qh) + (size_t)(b * NT + q0 + r) * NH + u * 8;
            qreg[l] = *(const uint4*)src;
        }
    }

    for (int qt = qt_begin; qt < qt_end; qt++) {
        const int q0 = qt * 64;
        __syncthreads();
#pragma unroll
        for (int l = 0; l < 4; l++) {
            int idx = tid + l * 256;
            int hilo = idx >> 9;
            int w = idx & 511, r = w >> 3, u = w & 7;
            *(uint4*)(sm + (hilo ? CS_QL : CS_QH) + swz128(r, u)) = qreg[l];
        }
        __syncthreads();
        if (qt + 1 < qt_end) {
            const int q1 = (qt + 1) * 64;
#pragma unroll
            for (int l = 0; l < 4; l++) {
                int idx = tid + l * 256;
                int hilo = idx >> 9;
                int w = idx & 511, r = w >> 3, u = w & 7;
                const __nv_bfloat16* src = (hilo ? g_ql : g_qh) + (size_t)(b * NT + q1 + r) * NH + u * 8;
                qreg[l] = *(const uint4*)src;
            }
        }

        float acc[2][4][4];
#pragma unroll
        for (int mi = 0; mi < 2; mi++)
#pragma unroll
            for (int ni = 0; ni < 4; ni++)
#pragma unroll
                for (int r = 0; r < 4; r++) acc[mi][ni][r] = 0.f;

#pragma unroll
        for (int s = 0; s < 4; s++) {
            uint32_t ah[2][4], al[2][4];
#pragma unroll
            for (int mi = 0; mi < 2; mi++) {
                int r = wm * 32 + mi * 16 + (lane & 15);
                int u = 2 * s + (lane >> 4);
                LDSM_X4(ah[mi][0], ah[mi][1], ah[mi][2], ah[mi][3], sb + CS_KH + swz128(r, u));
                LDSM_X4(al[mi][0], al[mi][1], al[mi][2], al[mi][3], sb + CS_KL + swz128(r, u));
            }
#pragma unroll
            for (int ni = 0; ni < 4; ni++) {
                int rB = wn * 32 + ni * 8 + (lane & 7);
                int u = 2 * s + ((lane >> 3) & 1);
                uint32_t bh[2], bl[2];
                LDSM_X2(bh[0], bh[1], sb + CS_QH + swz128(rB, u));
                LDSM_X2(bl[0], bl[1], sb + CS_QL + swz128(rB, u));
#pragma unroll
                for (int mi = 0; mi < 2; mi++) {
                    MMA_BF16(acc[mi][ni], ah[mi], bh);
                    MMA_BF16(acc[mi][ni], ah[mi], bl);
                    MMA_BF16(acc[mi][ni], al[mi], bh);
                }
            }
        }

        const bool full = (q0 >= k0 + 128);
#pragma unroll
        for (int mi = 0; mi < 2; mi++) {
#pragma unroll
            for (int ni = 0; ni < 4; ni++) {
                int qg = q0 + wn * 32 + ni * 8 + 2 * (lane & 3);
#pragma unroll
                for (int half = 0; half < 2; half++) {
                    int kg = k0 + wm * 32 + mi * 16 + (lane >> 2) + 8 * half;
                    float d0 = acc[mi][ni][2 * half];
                    float d1 = acc[mi][ni][2 * half + 1];
                    float e0 = (full || qg >= kg) ? __expf(d0 * SCALE) : 0.f;
                    float e1 = (full || qg + 1 >= kg) ? __expf(d1 * SCALE) : 0.f;
                    csum[mi * 2 + half] += e0 + e1;
                }
            }
        }
    }

#pragma unroll
    for (int i = 0; i < 4; i++) {
        csum[i] += __shfl_xor_sync(0xFFFFFFFF, csum[i], 1);
        csum[i] += __shfl_xor_sync(0xFFFFFFFF, csum[i], 2);
    }
    __syncthreads();
    float* red = (float*)(sm + CS_RED);
    if ((lane & 3) == 0) {
#pragma unroll
        for (int mi = 0; mi < 2; mi++)
#pragma unroll
            for (int half = 0; half < 2; half++)
                red[wn * 128 + wm * 32 + mi * 16 + (lane >> 2) + 8 * half] = csum[mi * 2 + half];
    }
    __syncthreads();
    if (tid < 128)
        g_part[(c * NB + b) * NT + k0 + tid] = red[tid] + red[128 + tid];
}

// ---------------------------------------------------------------------------
// Kernel 3: fused out, uniform paired scheduling + 3-stage cp.async pipeline
// (ONE sync per tile-step) + rinv computed in-kernel into smem (rinv_kernel
// deleted). Body otherwise identical to R16.
// smem 120KB: QH 8K | QL 8K | RV 8K | stage{0,1,2}: KH 8K KL 8K VH 8K VL 8K.
// ---------------------------------------------------------------------------
#define OQH 0
#define OQL 8192
#define ORV 16384
#define OSTG(s) (24576 + (s) * 32768)
#define ORED OSTG(0)             // reduction reuses drained stage area
#define OUT_SMEM 122880

__global__ __launch_bounds__(512) void out_kernel(float* __restrict__ out) {
    extern __shared__ __align__(16) char sm[];
    const uint32_t sb = smem_u32(sm);

    const int tid  = threadIdx.x;
    const int wid  = tid >> 5;
    const int lane = tid & 31;
    const int pair = blockIdx.x;     // 0..15
    const int b    = blockIdx.y;
    const int wm = wid >> 2;         // q-group (16 rows)
    const int wk = wid & 3;          // k-quarter (16 cols)

    auto issue_tile = [&](int kt, int s) {
        const int k0 = kt * 64;
#pragma unroll
        for (int l = 0; l < 4; l++) {
            int idx = tid + l * 512;
            int arr = idx >> 9;                      // 0:KH 1:KL 2:VH 3:VL
            int w = idx & 511, r = w >> 3, u = w & 7;
            const __nv_bfloat16* src =
                (arr == 0) ? g_kh + (size_t)(b * NT + k0 + r) * NH + u * 8 :
                (arr == 1) ? g_kl + (size_t)(b * NT + k0 + r) * NH + u * 8 :
                (arr == 2) ? g_vh + (size_t)(b * NT + k0 + r) * NH + u * 8 :
                             g_vl + (size_t)(b * NT + k0 + r) * NH + u * 8;
            cp_async16(sb + OSTG(s) + arr * 8192 + swz128(r, u), src);
        }
        CP_COMMIT();
    };

    // rinv -> smem once (replaces rinv_kernel): 4 elements per thread
    {
        float* rvs = (float*)(sm + ORV);
#pragma unroll
        for (int l = 0; l < 4; l++) {
            int k = tid + l * 512;
            float s = g_part[(0 * NB + b) * NT + k] + g_part[(1 * NB + b) * NT + k]
                    + g_part[(2 * NB + b) * NT + k] + g_part[(3 * NB + b) * NT + k];
            rvs[k] = 1.f / s;
        }
    }

    for (int ph = 0; ph < 2; ph++) {
        const int qt = ph ? (NTILES - 1 - pair) : pair;
        const int q0 = qt * 64;

        if (ph) __syncthreads();     // phase-0 reduction reads done before
                                     // stage area (aliases red) is re-issued
        // Prologue: 2 tiles in flight
        issue_tile(0, 0);
        if (qt >= 1) issue_tile(1, 1);

        // Q tile -> smem (hi/lo)
#pragma unroll
        for (int l = 0; l < 2; l++) {
            int idx = tid + l * 512;
            int hilo = idx >> 9;
            int w = idx & 511, r = w >> 3, u = w & 7;
            const __nv_bfloat16* src = (hilo ? g_ql : g_qh) + (size_t)(b * NT + q0 + r) * NH + u * 8;
            *(uint4*)(sm + (hilo ? OQL : OQH) + swz128(r, u)) = *(const uint4*)src;
        }
        __syncthreads();             // Q + rv visible

        // Hoisted Q A-frags (loop-invariant): 4 h-k16-steps x hi/lo
        uint32_t qfh[4][4], qfl[4][4];
        {
            int rA = wm * 16 + (lane & 15);
#pragma unroll
            for (int ks = 0; ks < 4; ks++) {
                int uA = 2 * ks + (lane >> 4);
                LDSM_X4(qfh[ks][0], qfh[ks][1], qfh[ks][2], qfh[ks][3], sb + OQH + swz128(rA, uA));
                LDSM_X4(qfl[ks][0], qfl[ks][1], qfl[ks][2], qfl[ks][3], sb + OQL + swz128(rA, uA));
            }
        }

        float acc[8][4];
#pragma unroll
        for (int nh = 0; nh < 8; nh++)
#pragma unroll
            for (int r = 0; r < 4; r++) acc[nh][r] = 0.f;

        const int qwlo = q0 + wm * 16;

        for (int kt = 0; kt <= qt; kt++) {
            const int s = kt % 3;
            if (kt < qt) CP_WAIT(1); else CP_WAIT(0);   // stage kt complete
            __syncthreads();         // all compute(kt-1) done; stage kt visible
            if (kt + 2 <= qt) issue_tile(kt + 2, (kt + 2) % 3);

            const int kb = kt * 64 + wk * 16;
            if (kb <= qwlo + 15) {   // else fully masked -> skip
                const uint32_t KH = sb + OSTG(s);
                const uint32_t KL = KH + 8192;
                const uint32_t VH = KH + 16384;
                const uint32_t VL = KH + 24576;

                float sacc[2][4];
#pragma unroll
                for (int ni = 0; ni < 2; ni++)
#pragma unroll
                    for (int r = 0; r < 4; r++) sacc[ni][r] = 0.f;

#pragma unroll
                for (int ks = 0; ks < 4; ks++) {
#pragma unroll
                    for (int ni = 0; ni < 2; ni++) {
                        int rB = wk * 16 + ni * 8 + (lane & 7);
                        int u = 2 * ks + ((lane >> 3) & 1);
                        uint32_t bh[2], bl[2];
                        LDSM_X2(bh[0], bh[1], KH + swz128(rB, u));
                        LDSM_X2(bl[0], bl[1], KL + swz128(rB, u));
                        MMA_BF16(sacc[ni], qfh[ks], bh);
                        MMA_BF16(sacc[ni], qfh[ks], bl);
                        MMA_BF16(sacc[ni], qfl[ks], bh);
                    }
                }

                const bool full = (kb + 15 <= qwlo);
                const int qgA = qwlo + (lane >> 2);
                uint32_t pah[4], pal[4];
#pragma unroll
                for (int ni = 0; ni < 2; ni++) {
                    int kg = kb + ni * 8 + 2 * (lane & 3);
                    float2 rvv = *(const float2*)(sm + ORV + (size_t)kg * 4);
                    float e0 = (full || qgA     >= kg    ) ? __expf(sacc[ni][0] * SCALE) * rvv.x : 0.f;
                    float e1 = (full || qgA     >= kg + 1) ? __expf(sacc[ni][1] * SCALE) * rvv.y : 0.f;
                    float e2 = (full || qgA + 8 >= kg    ) ? __expf(sacc[ni][2] * SCALE) * rvv.x : 0.f;
                    float e3 = (full || qgA + 8 >= kg + 1) ? __expf(sacc[ni][3] * SCALE) * rvv.y : 0.f;
                    __nv_bfloat16 h0, l0, h1, l1, h2, l2, h3, l3;
                    bf16split(e0, h0, l0); bf16split(e1, h1, l1);
                    bf16split(e2, h2, l2); bf16split(e3, h3, l3);
                    pah[ni * 2 + 0] = packbf(h0, h1); pah[ni * 2 + 1] = packbf(h2, h3);
                    pal[ni * 2 + 0] = packbf(l0, l1); pal[ni * 2 + 1] = packbf(l2, l3);
                }

                int rB = wk * 16 + (lane & 7) + 8 * ((lane >> 3) & 1);
#pragma unroll
                for (int nh = 0; nh < 8; nh++) {
                    uint32_t vh[2], vl[2];
                    LDSM_X2_T(vh[0], vh[1], VH + swz128(rB, nh));
                    LDSM_X2_T(vl[0], vl[1], VL + swz128(rB, nh));
                    MMA_BF16(acc[nh], pah, vh);
                    MMA_BF16(acc[nh], pah, vl);
                    MMA_BF16(acc[nh], pal, vh);
                }
            }
        }
        __syncthreads();             // all compute done; stages drained -> red

        // Reduce over k-quarters: wk=1..3 -> 3 smem buffers, wk=0 adds+writes.
        float* red = (float*)(sm + ORED);
        if (wk) {
            float* buf = red + (wk - 1) * 4352;      // 68*64 floats
#pragma unroll
            for (int nh = 0; nh < 8; nh++) {
                int h = nh * 8 + 2 * (lane & 3);
                int row = wm * 16 + (lane >> 2);
                buf[row * 68 + h]       = acc[nh][0];
                buf[row * 68 + h + 1]   = acc[nh][1];
                buf[(row + 8) * 68 + h]     = acc[nh][2];
                buf[(row + 8) * 68 + h + 1] = acc[nh][3];
            }
        }
        __syncthreads();
        if (wk == 0) {
#pragma unroll
            for (int nh = 0; nh < 8; nh++) {
                int h = nh * 8 + 2 * (lane & 3);
                int row = wm * 16 + (lane >> 2);
                float2 v0, v1;
                v0.x = acc[nh][0] + red[row * 68 + h]     + red[4352 + row * 68 + h]     + red[8704 + row * 68 + h];
                v0.y = acc[nh][1] + red[row * 68 + h + 1] + red[4352 + row * 68 + h + 1] + red[8704 + row * 68 + h + 1];
                v1.x = acc[nh][2] + red[(row + 8) * 68 + h]     + red[4352 + (row + 8) * 68 + h]     + red[8704 + (row + 8) * 68 + h];
                v1.y = acc[nh][3] + red[(row + 8) * 68 + h + 1] + red[4352 + (row + 8) * 68 + h + 1] + red[8704 + (row + 8) * 68 + h + 1];
                *(float2*)(out + (size_t)(b * NT + q0 + row) * NH + h) = v0;
                *(float2*)(out + (size_t)(b * NT + q0 + row + 8) * NH + h) = v1;
            }
        }
    }
}

// ---------------------------------------------------------------------------
// Launch (graph-capturable, allocation-free, atomic-free -> deterministic).
// Input order per metadata: x, Wk, Wq, Wv.
// ---------------------------------------------------------------------------
extern "C" void kernel_launch(void* const* d_in, const int* in_sizes, int n_in,
                              void* d_out, int out_size) {
    const float* x  = (const float*)d_in[0];
    const float* Wk = (const float*)d_in[1];
    const float* Wq = (const float*)d_in[2];
    const float* Wv = (const float*)d_in[3];
    float* out = (float*)d_out;

    cudaFuncSetAttribute(projmma_kernel,
                         cudaFuncAttributeMaxDynamicSharedMemorySize, PJ_SMEM);
    cudaFuncSetAttribute(out_kernel,
                         cudaFuncAttributeMaxDynamicSharedMemorySize, OUT_SMEM);

    wconv_kernel<<<48, 256>>>(Wq, Wk, Wv);
    projmma_kernel<<<(NB * NT) / 128, 256, PJ_SMEM>>>(x);
    colsum_kernel<<<dim3(KT128, QCHUNK, NB), 256>>>();
    out_kernel<<<dim3(NTILES / 2, NB), 512, OUT_SMEM>>>(out);
}